// round 9
// baseline (speedup 1.0000x reference)
#include <cuda_runtime.h>
#include <cuda_bf16.h>
#include <cuda_fp16.h>
#include <math.h>

#define N_NODES 100000
#define N_EDGES 1600000
#define DIMF    128
#define OUTD_F  40

// ---------------- scratch (device globals; no allocation allowed) ----------
__device__ int   g_is64;
__device__ int   g_deg[N_NODES];
__device__ float g_invdeg[N_NODES];
__device__ int   g_off[N_NODES + 1];
__device__ int   g_cursor[N_NODES];
__device__ int   g_csc[N_EDGES];
__device__ __align__(16) unsigned short g_Ub[(size_t)N_NODES * DIMF]; // X@Wl^T, bf16 bits
__device__ __align__(16) float  g_V [(size_t)N_NODES * DIMF];          // X@Wr^T + b
__device__ __align__(16) __half g_uh[(size_t)N_NODES * OUTD_F];        // layer2: h1@Wl2^T
__device__ __align__(16) float  g_v [(size_t)N_NODES * OUTD_F];        // layer2: h1@Wr2^T + b2
// bf16 split operands for tensor-core GEMM (per-layer weight buffers)
__device__ __align__(16) __nv_bfloat16 g_xhi[(size_t)N_NODES * DIMF];
__device__ __align__(16) __nv_bfloat16 g_xlo[(size_t)N_NODES * DIMF];
__device__ __align__(16) __nv_bfloat16 g_W0lhi[DIMF*DIMF], g_W0llo[DIMF*DIMF];
__device__ __align__(16) __nv_bfloat16 g_W0rhi[DIMF*DIMF], g_W0rlo[DIMF*DIMF];
__device__ __align__(16) __nv_bfloat16 g_W1lhi[DIMF*DIMF], g_W1llo[DIMF*DIMF];
__device__ __align__(16) __nv_bfloat16 g_W1rhi[DIMF*DIMF], g_W1rlo[DIMF*DIMF];
__device__ __align__(16) __nv_bfloat16 g_W2hi[2*OUTD_F*DIMF], g_W2lo[2*OUTD_F*DIMF];

__device__ __forceinline__ int edge_at(const int* __restrict__ e32, int i) {
    return g_is64 ? e32[2 * i] : e32[i];
}
__device__ __forceinline__ void split2(float v, __nv_bfloat16& hi, __nv_bfloat16& lo) {
    hi = __float2bfloat16(v);
    lo = __float2bfloat16(v - __bfloat162float(hi));
}
// bf16-pair unpack via integer ops (no F2F, no register reinterpret)
__device__ __forceinline__ float bf_lo(unsigned w) { return __uint_as_float(w << 16); }
__device__ __forceinline__ float bf_hi(unsigned w) { return __uint_as_float(w & 0xFFFF0000u); }
__device__ __forceinline__ unsigned bf_pack(float a, float b) {
    return (unsigned)__bfloat16_as_ushort(__float2bfloat16(a)) |
           ((unsigned)__bfloat16_as_ushort(__float2bfloat16(b)) << 16);
}

// ---------------- init: zero degree + dtype detect -------------------------
__global__ void k_init(const int* __restrict__ e32) {
    int i = blockIdx.x * blockDim.x + threadIdx.x;
    if (i < N_NODES) g_deg[i] = 0;
    if (blockIdx.x == 0) {
        __shared__ int nz;
        if (threadIdx.x == 0) nz = 0;
        __syncthreads();
        for (int k = threadIdx.x; k < 1024; k += blockDim.x)
            if (e32[2 * k + 1] != 0) nz = 1;
        __syncthreads();
        if (threadIdx.x == 0) g_is64 = (nz == 0);
    }
}

__global__ void k_hist(const int* __restrict__ e32) {
    int e = blockIdx.x * blockDim.x + threadIdx.x;
    if (e < N_EDGES) {
        int d = edge_at(e32, N_EDGES + e);
        if ((unsigned)d < N_NODES) atomicAdd(&g_deg[d], 1);
    }
}

// single-block full scan: offsets, cursor, invdeg (no serial 1-thread pass)
__global__ void k_scan_all() {
    __shared__ int ssum[1024];
    const int CH = 98;                       // 1024*98 >= 100000
    int t = threadIdx.x;
    int beg = t * CH;
    int end = beg + CH < N_NODES ? beg + CH : N_NODES;
    if (beg > N_NODES) beg = N_NODES;
    int s = 0;
    for (int i = beg; i < end; i++) s += g_deg[i];
    ssum[t] = s;
    __syncthreads();
    for (int st = 1; st < 1024; st <<= 1) {
        int p = (t >= st) ? ssum[t - st] : 0;
        __syncthreads();
        ssum[t] += p;
        __syncthreads();
    }
    int base = (t == 0) ? 0 : ssum[t - 1];
    for (int i = beg; i < end; i++) {
        g_off[i] = base;
        g_cursor[i] = base;
        int d = g_deg[i];
        base += d;
        g_invdeg[i] = 1.0f / (float)(d > 1 ? d : 1);
    }
    if (t == 1023) g_off[N_NODES] = N_EDGES;
}

__global__ void k_fill_csc(const int* __restrict__ e32) {
    int e = blockIdx.x * blockDim.x + threadIdx.x;
    if (e < N_EDGES) {
        int s = edge_at(e32, e);
        int d = edge_at(e32, N_EDGES + e);
        if ((unsigned)s < N_NODES && (unsigned)d < N_NODES) {
            int p = atomicAdd(&g_cursor[d], 1);
            g_csc[p] = s;
        }
    }
}

// ---------------- operand splitting -----------------------------------------
__global__ void k_split_x(const float* __restrict__ x) {
    for (size_t i = (size_t)blockIdx.x * blockDim.x + threadIdx.x;
         i < (size_t)N_NODES * DIMF; i += (size_t)gridDim.x * blockDim.x) {
        __nv_bfloat16 hi, lo; split2(x[i], hi, lo);
        g_xhi[i] = hi; g_xlo[i] = lo;
    }
}

// all three layers' weights in one launch, separate buffers
__global__ void k_split_weights(const float* __restrict__ Wl0, const float* __restrict__ Wr0,
                                const float* __restrict__ Wl1, const float* __restrict__ Wr1,
                                const float* __restrict__ Wl2, const float* __restrict__ Wr2) {
    int i = blockIdx.x * blockDim.x + threadIdx.x;
    __nv_bfloat16 h, l;
    if (i < DIMF * DIMF) {
        split2(Wl0[i], h, l); g_W0lhi[i] = h; g_W0llo[i] = l;
        split2(Wr0[i], h, l); g_W0rhi[i] = h; g_W0rlo[i] = l;
        split2(Wl1[i], h, l); g_W1lhi[i] = h; g_W1llo[i] = l;
        split2(Wr1[i], h, l); g_W1rhi[i] = h; g_W1rlo[i] = l;
    }
    if (i < OUTD_F * DIMF) {
        split2(Wl2[i], h, l); g_W2hi[i] = h; g_W2lo[i] = l;
        split2(Wr2[i], h, l); g_W2hi[OUTD_F * DIMF + i] = h; g_W2lo[OUTD_F * DIMF + i] = l;
    }
}

// ---------------- tensor-core GEMM ------------------------------------------
__device__ __forceinline__ void mma_bf16(float* d, const unsigned* a, unsigned b0, unsigned b1) {
    asm volatile(
        "mma.sync.aligned.m16n8k16.row.col.f32.bf16.bf16.f32 "
        "{%0,%1,%2,%3}, {%4,%5,%6,%7}, {%8,%9}, {%0,%1,%2,%3};\n"
        : "+f"(d[0]), "+f"(d[1]), "+f"(d[2]), "+f"(d[3])
        : "r"(a[0]), "r"(a[1]), "r"(a[2]), "r"(a[3]), "r"(b0), "r"(b1));
}

// layers 0/1: blockIdx.y==0 -> U(bf16) = X@Wl^T ; ==1 -> V(f32) = X@Wr^T + b
__global__ void __launch_bounds__(256) k_gemm_l01(const float* __restrict__ bias, int layer) {
    constexpr int OUTD = 128;
    constexpr int MT = 2, NT = 8, STR = 20;

    __shared__ __align__(16) unsigned sAh[128 * STR], sAl[128 * STR];
    __shared__ __align__(16) unsigned sWh[OUTD * STR], sWl[OUTD * STR];

    int side = blockIdx.y;
    const unsigned* Ah = (const unsigned*)g_xhi;
    const unsigned* Al = (const unsigned*)g_xlo;
    const unsigned* Wh;
    const unsigned* Wo;
    if (layer == 0) {
        Wh = (const unsigned*)(side ? g_W0rhi : g_W0lhi);
        Wo = (const unsigned*)(side ? g_W0rlo : g_W0llo);
    } else {
        Wh = (const unsigned*)(side ? g_W1rhi : g_W1lhi);
        Wo = (const unsigned*)(side ? g_W1rlo : g_W1llo);
    }

    int tid  = threadIdx.x;
    int wid  = tid >> 5, lane = tid & 31;
    int mw   = wid & 3, nw = wid >> 2;
    int row0 = blockIdx.x * 128;
    int lg   = lane >> 2, lt = lane & 3;

    float acc[MT][NT][4];
#pragma unroll
    for (int m = 0; m < MT; m++)
#pragma unroll
        for (int n = 0; n < NT; n++)
#pragma unroll
            for (int q = 0; q < 4; q++) acc[m][n][q] = 0.f;

#pragma unroll 1
    for (int kt = 0; kt < 4; kt++) {
        int kw = kt * 16;

#pragma unroll
        for (int i = tid; i < 128 * 4; i += 256) {
            int r = i >> 2, q = (i & 3) * 4;
            uint4 vh = make_uint4(0, 0, 0, 0), vl = vh;
            if (row0 + r < N_NODES) {
                vh = *(const uint4*)(Ah + (size_t)(row0 + r) * 64 + kw + q);
                vl = *(const uint4*)(Al + (size_t)(row0 + r) * 64 + kw + q);
            }
            *(uint4*)(sAh + r * STR + q) = vh;
            *(uint4*)(sAl + r * STR + q) = vl;
        }
        for (int i = tid; i < OUTD * 4; i += 256) {
            int r = i >> 2, q = (i & 3) * 4;
            *(uint4*)(sWh + r * STR + q) = *(const uint4*)(Wh + (size_t)r * 64 + kw + q);
            *(uint4*)(sWl + r * STR + q) = *(const uint4*)(Wo + (size_t)r * 64 + kw + q);
        }
        __syncthreads();

#pragma unroll
        for (int ks = 0; ks < 2; ks++) {
            int wb = ks * 8;
            unsigned ah[MT][4], al[MT][4];
#pragma unroll
            for (int m = 0; m < MT; m++) {
                int rr = (mw * MT + m) * 16 + lg;
                ah[m][0] = sAh[rr * STR + wb + lt];
                ah[m][1] = sAh[(rr + 8) * STR + wb + lt];
                ah[m][2] = sAh[rr * STR + wb + 4 + lt];
                ah[m][3] = sAh[(rr + 8) * STR + wb + 4 + lt];
                al[m][0] = sAl[rr * STR + wb + lt];
                al[m][1] = sAl[(rr + 8) * STR + wb + lt];
                al[m][2] = sAl[rr * STR + wb + 4 + lt];
                al[m][3] = sAl[(rr + 8) * STR + wb + 4 + lt];
            }
#pragma unroll
            for (int n = 0; n < NT; n++) {
                int nr = nw * NT * 8 + n * 8 + lg;
                unsigned bh0 = sWh[nr * STR + wb + lt];
                unsigned bh1 = sWh[nr * STR + wb + 4 + lt];
                unsigned bl0 = sWl[nr * STR + wb + lt];
                unsigned bl1 = sWl[nr * STR + wb + 4 + lt];
#pragma unroll
                for (int m = 0; m < MT; m++) {
                    mma_bf16(acc[m][n], ah[m], bh0, bh1);
                    mma_bf16(acc[m][n], ah[m], bl0, bl1);
                    mma_bf16(acc[m][n], al[m], bh0, bh1);
                }
            }
        }
        __syncthreads();
    }

#pragma unroll
    for (int m = 0; m < MT; m++) {
        int r = row0 + (mw * MT + m) * 16 + lg;
#pragma unroll
        for (int n = 0; n < NT; n++) {
            int c = nw * NT * 8 + n * 8 + lt * 2;
#pragma unroll
            for (int h = 0; h < 2; h++) {
                int rr = r + h * 8;
                if (rr >= N_NODES) continue;
                float v0 = acc[m][n][h * 2], v1 = acc[m][n][h * 2 + 1];
                if (side) {
                    g_V[(size_t)rr * OUTD + c]     = v0 + bias[c];
                    g_V[(size_t)rr * OUTD + c + 1] = v1 + bias[c + 1];
                } else {
                    *(unsigned*)(g_Ub + (size_t)rr * OUTD + c) = bf_pack(v0, v1);
                }
            }
        }
    }
}

// layer 2: [u|v] = h1 @ [Wl2;Wr2]^T; u -> fp16, v -> f32 + bias
__global__ void __launch_bounds__(256) k_gemm2(const float* __restrict__ bias) {
    constexpr int OUTD = 80;
    constexpr int MT = 2, NT = 5, STR = 20;

    __shared__ __align__(16) unsigned sAh[128 * STR], sAl[128 * STR];
    __shared__ __align__(16) unsigned sWh[OUTD * STR], sWl[OUTD * STR];

    int tid  = threadIdx.x;
    int wid  = tid >> 5, lane = tid & 31;
    int mw   = wid & 3, nw = wid >> 2;
    int row0 = blockIdx.x * 128;
    int lg   = lane >> 2, lt = lane & 3;

    float acc[MT][NT][4];
#pragma unroll
    for (int m = 0; m < MT; m++)
#pragma unroll
        for (int n = 0; n < NT; n++)
#pragma unroll
            for (int q = 0; q < 4; q++) acc[m][n][q] = 0.f;

    const unsigned* Ah = (const unsigned*)g_xhi;
    const unsigned* Al = (const unsigned*)g_xlo;
    const unsigned* Wh = (const unsigned*)g_W2hi;
    const unsigned* Wo = (const unsigned*)g_W2lo;

#pragma unroll 1
    for (int kt = 0; kt < 4; kt++) {
        int kw = kt * 16;

#pragma unroll
        for (int i = tid; i < 128 * 4; i += 256) {
            int r = i >> 2, q = (i & 3) * 4;
            uint4 vh = make_uint4(0, 0, 0, 0), vl = vh;
            if (row0 + r < N_NODES) {
                vh = *(const uint4*)(Ah + (size_t)(row0 + r) * 64 + kw + q);
                vl = *(const uint4*)(Al + (size_t)(row0 + r) * 64 + kw + q);
            }
            *(uint4*)(sAh + r * STR + q) = vh;
            *(uint4*)(sAl + r * STR + q) = vl;
        }
        for (int i = tid; i < OUTD * 4; i += 256) {
            int r = i >> 2, q = (i & 3) * 4;
            *(uint4*)(sWh + r * STR + q) = *(const uint4*)(Wh + (size_t)r * 64 + kw + q);
            *(uint4*)(sWl + r * STR + q) = *(const uint4*)(Wo + (size_t)r * 64 + kw + q);
        }
        __syncthreads();

#pragma unroll
        for (int ks = 0; ks < 2; ks++) {
            int wb = ks * 8;
            unsigned ah[MT][4], al[MT][4];
#pragma unroll
            for (int m = 0; m < MT; m++) {
                int rr = (mw * MT + m) * 16 + lg;
                ah[m][0] = sAh[rr * STR + wb + lt];
                ah[m][1] = sAh[(rr + 8) * STR + wb + lt];
                ah[m][2] = sAh[rr * STR + wb + 4 + lt];
                ah[m][3] = sAh[(rr + 8) * STR + wb + 4 + lt];
                al[m][0] = sAl[rr * STR + wb + lt];
                al[m][1] = sAl[(rr + 8) * STR + wb + lt];
                al[m][2] = sAl[rr * STR + wb + 4 + lt];
                al[m][3] = sAl[(rr + 8) * STR + wb + 4 + lt];
            }
#pragma unroll
            for (int n = 0; n < NT; n++) {
                int nr = nw * NT * 8 + n * 8 + lg;
                unsigned bh0 = sWh[nr * STR + wb + lt];
                unsigned bh1 = sWh[nr * STR + wb + 4 + lt];
                unsigned bl0 = sWl[nr * STR + wb + lt];
                unsigned bl1 = sWl[nr * STR + wb + 4 + lt];
#pragma unroll
                for (int m = 0; m < MT; m++) {
                    mma_bf16(acc[m][n], ah[m], bh0, bh1);
                    mma_bf16(acc[m][n], ah[m], bl0, bl1);
                    mma_bf16(acc[m][n], al[m], bh0, bh1);
                }
            }
        }
        __syncthreads();
    }

#pragma unroll
    for (int m = 0; m < MT; m++) {
        int r = row0 + (mw * MT + m) * 16 + lg;
#pragma unroll
        for (int n = 0; n < NT; n++) {
            int c = nw * NT * 8 + n * 8 + lt * 2;
#pragma unroll
            for (int h = 0; h < 2; h++) {
                int rr = r + h * 8;
                if (rr >= N_NODES) continue;
                float v0 = acc[m][n][h * 2], v1 = acc[m][n][h * 2 + 1];
                if (c < OUTD_F) {
                    *(__half2*)(g_uh + (size_t)rr * OUTD_F + c) = __floats2half2_rn(v0, v1);
                } else {
                    g_v[(size_t)rr * OUTD_F + c - OUTD_F]     = v0 + bias[c - OUTD_F];
                    g_v[(size_t)rr * OUTD_F + c - OUTD_F + 1] = v1 + bias[c - OUTD_F + 1];
                }
            }
        }
    }
}

// ---------------- fused: gather-mean(U bf16) + V, L2-norm, ReLU, split -----
// one warp per node; lane handles cols [4*lane, 4*lane+3]; 4-deep MLP.
__global__ void k_aggnorm() {
    int warp = (blockIdx.x * blockDim.x + threadIdx.x) >> 5;
    int lane = threadIdx.x & 31;
    if (warp >= N_NODES) return;
    int n = warp;
    const uint2* U2 = (const uint2*)g_Ub;    // row = 32 uint2 (128 bf16)
    int j = g_off[n], je = g_off[n + 1];
    float ax = 0.f, ay = 0.f, az = 0.f, aw = 0.f;
    for (; j + 3 < je; j += 4) {
        int s0 = g_csc[j], s1 = g_csc[j + 1], s2 = g_csc[j + 2], s3 = g_csc[j + 3];
        uint2 w0 = U2[(size_t)s0 * 32 + lane];
        uint2 w1 = U2[(size_t)s1 * 32 + lane];
        uint2 w2 = U2[(size_t)s2 * 32 + lane];
        uint2 w3 = U2[(size_t)s3 * 32 + lane];
        ax += bf_lo(w0.x) + bf_lo(w1.x) + bf_lo(w2.x) + bf_lo(w3.x);
        ay += bf_hi(w0.x) + bf_hi(w1.x) + bf_hi(w2.x) + bf_hi(w3.x);
        az += bf_lo(w0.y) + bf_lo(w1.y) + bf_lo(w2.y) + bf_lo(w3.y);
        aw += bf_hi(w0.y) + bf_hi(w1.y) + bf_hi(w2.y) + bf_hi(w3.y);
    }
    for (; j < je; j++) {
        uint2 w0 = U2[(size_t)g_csc[j] * 32 + lane];
        ax += bf_lo(w0.x); ay += bf_hi(w0.x);
        az += bf_lo(w0.y); aw += bf_hi(w0.y);
    }
    float inv_d = g_invdeg[n];
    float4 vv = ((const float4*)g_V)[(size_t)n * 32 + lane];
    ax = ax * inv_d + vv.x;
    ay = ay * inv_d + vv.y;
    az = az * inv_d + vv.z;
    aw = aw * inv_d + vv.w;

    float ss = ax * ax + ay * ay + az * az + aw * aw;
#pragma unroll
    for (int s = 16; s; s >>= 1) ss += __shfl_xor_sync(0xFFFFFFFFu, ss, s);
    float sc = 1.0f / fmaxf(sqrtf(ss), 1e-12f);
    ax = fmaxf(ax * sc, 0.f);
    ay = fmaxf(ay * sc, 0.f);
    az = fmaxf(az * sc, 0.f);
    aw = fmaxf(aw * sc, 0.f);

    size_t idx = (size_t)n * DIMF + lane * 4;
    __nv_bfloat16 hi, lo;
    split2(ax, hi, lo); g_xhi[idx]     = hi; g_xlo[idx]     = lo;
    split2(ay, hi, lo); g_xhi[idx + 1] = hi; g_xlo[idx + 1] = lo;
    split2(az, hi, lo); g_xhi[idx + 2] = hi; g_xlo[idx + 2] = lo;
    split2(aw, hi, lo); g_xhi[idx + 3] = hi; g_xlo[idx + 3] = lo;
}

// ---------------- layer-2: gather u(fp16), add v, softmax ------------------
__global__ void k_agg_softmax(float* __restrict__ out) {
    int warp = (blockIdx.x * blockDim.x + threadIdx.x) >> 5;
    int lane = threadIdx.x & 31;
    if (warp >= N_NODES) return;
    int n = warp;
    bool act = lane < 20;                    // 2 cols per active lane
    const __half2* u2 = (const __half2*)g_uh;   // row = 20 half2
    int j = g_off[n], je = g_off[n + 1];
    float acc0 = 0.f, acc1 = 0.f;
    for (; j + 3 < je; j += 4) {
        int s0 = g_csc[j], s1 = g_csc[j + 1], s2 = g_csc[j + 2], s3 = g_csc[j + 3];
        if (act) {
            float2 f0 = __half22float2(u2[(size_t)s0 * 20 + lane]);
            float2 f1 = __half22float2(u2[(size_t)s1 * 20 + lane]);
            float2 f2 = __half22float2(u2[(size_t)s2 * 20 + lane]);
            float2 f3 = __half22float2(u2[(size_t)s3 * 20 + lane]);
            acc0 += f0.x + f1.x + f2.x + f3.x;
            acc1 += f0.y + f1.y + f2.y + f3.y;
        }
    }
    for (; j < je; j++) {
        int s0 = g_csc[j];
        if (act) {
            float2 f0 = __half22float2(u2[(size_t)s0 * 20 + lane]);
            acc0 += f0.x; acc1 += f0.y;
        }
    }
    float inv_d = g_invdeg[n];
    float a0 = -1e30f, a1 = -1e30f;
    if (act) {
        a0 = acc0 * inv_d + g_v[(size_t)n * OUTD_F + lane * 2];
        a1 = acc1 * inv_d + g_v[(size_t)n * OUTD_F + lane * 2 + 1];
    }
    float m = fmaxf(a0, a1);
#pragma unroll
    for (int s = 16; s; s >>= 1) m = fmaxf(m, __shfl_xor_sync(0xFFFFFFFFu, m, s));
    float e0 = act ? __expf(a0 - m) : 0.f;
    float e1 = act ? __expf(a1 - m) : 0.f;
    float sum = e0 + e1;
#pragma unroll
    for (int s = 16; s; s >>= 1) sum += __shfl_xor_sync(0xFFFFFFFFu, sum, s);
    float inv = 1.0f / sum;
    if (act) {
        float* row = out + (size_t)n * OUTD_F + lane * 2;
        row[0] = e0 * inv;
        row[1] = e1 * inv;
    }
}

// ---------------- launch ----------------------------------------------------
extern "C" void kernel_launch(void* const* d_in, const int* in_sizes, int n_in,
                              void* d_out, int out_size) {
    const float* x   = (const float*)d_in[0];
    const int*   e32 = (const int*)d_in[1];
    const float* Wl0 = (const float*)d_in[2];
    const float* Wr0 = (const float*)d_in[3];
    const float* b0  = (const float*)d_in[4];
    const float* Wl1 = (const float*)d_in[5];
    const float* Wr1 = (const float*)d_in[6];
    const float* b1  = (const float*)d_in[7];
    const float* Wl2 = (const float*)d_in[8];
    const float* Wr2 = (const float*)d_in[9];
    const float* b2  = (const float*)d_in[10];
    float* out = (float*)d_out;

    const int TB = 256;
    int nblk_nodes = (N_NODES + TB - 1) / TB;
    int nblk_edges = (N_EDGES + TB - 1) / TB;
    int nblk_gemm  = (N_NODES + 127) / 128;    // 782
    int nblk_wnode = (N_NODES + 7) / 8;        // warp-per-node

    // ---- build CSC (4 launches) ----
    k_init<<<nblk_nodes, TB>>>(e32);
    k_hist<<<nblk_edges, TB>>>(e32);
    k_scan_all<<<1, 1024>>>();
    k_fill_csc<<<nblk_edges, TB>>>(e32);

    // ---- operand prep (2 launches) ----
    k_split_x<<<2048, TB>>>(x);
    k_split_weights<<<(DIMF * DIMF + TB - 1) / TB, TB>>>(Wl0, Wr0, Wl1, Wr1, Wl2, Wr2);

    // ---- layer 0 ----
    k_gemm_l01<<<dim3(nblk_gemm, 2), TB>>>(b0, 0);
    k_aggnorm<<<nblk_wnode, TB>>>();

    // ---- layer 1 ----
    k_gemm_l01<<<dim3(nblk_gemm, 2), TB>>>(b1, 1);
    k_aggnorm<<<nblk_wnode, TB>>>();

    // ---- layer 2 ----
    k_gemm2<<<nblk_gemm, TB>>>(b2);
    k_agg_softmax<<<nblk_wnode, TB>>>(out);
}

// round 10
// speedup vs baseline: 1.7655x; 1.7655x over previous
#include <cuda_runtime.h>
#include <cuda_bf16.h>
#include <cuda_fp16.h>
#include <math.h>

#define N_NODES 100000
#define N_EDGES 1600000
#define DIMF    128
#define OUTD_F  40
#define SCAN_B  1024
#define NB_SCAN 98   // ceil(100000/1024)

// ---------------- scratch (device globals; no allocation allowed) ----------
__device__ int   g_is64;
__device__ int   g_deg[N_NODES];
__device__ float g_invdeg[N_NODES];
__device__ int   g_off[N_NODES + 1];
__device__ int   g_cursor[N_NODES];
__device__ int   g_bsums[NB_SCAN];
__device__ int   g_csc[N_EDGES];
__device__ __align__(16) unsigned short g_Ub[(size_t)N_NODES * DIMF]; // X@Wl^T, bf16 bits
__device__ __align__(16) float  g_V [(size_t)N_NODES * DIMF];          // X@Wr^T + b
__device__ __align__(16) __half g_uh[(size_t)N_NODES * OUTD_F];        // layer2: h1@Wl2^T
__device__ __align__(16) float  g_v [(size_t)N_NODES * OUTD_F];        // layer2: h1@Wr2^T + b2
// bf16 split operands for tensor-core GEMM
__device__ __align__(16) __nv_bfloat16 g_xhi[(size_t)N_NODES * DIMF];
__device__ __align__(16) __nv_bfloat16 g_xlo[(size_t)N_NODES * DIMF];
__device__ __align__(16) __nv_bfloat16 g_Wlhi[DIMF * DIMF], g_Wllo[DIMF * DIMF];
__device__ __align__(16) __nv_bfloat16 g_Wrhi[DIMF * DIMF], g_Wrlo[DIMF * DIMF];

__device__ __forceinline__ int edge_at(const int* __restrict__ e32, int i) {
    return g_is64 ? e32[2 * i] : e32[i];
}
__device__ __forceinline__ void split2(float v, __nv_bfloat16& hi, __nv_bfloat16& lo) {
    hi = __float2bfloat16(v);
    lo = __float2bfloat16(v - __bfloat162float(hi));
}
// bf16-pair unpack via integer ops (no F2F, no register reinterpret)
__device__ __forceinline__ float bf_lo(unsigned w) { return __uint_as_float(w << 16); }
__device__ __forceinline__ float bf_hi(unsigned w) { return __uint_as_float(w & 0xFFFF0000u); }
__device__ __forceinline__ unsigned bf_pack(float a, float b) {
    return (unsigned)__bfloat16_as_ushort(__float2bfloat16(a)) |
           ((unsigned)__bfloat16_as_ushort(__float2bfloat16(b)) << 16);
}

// ---------------- dtype detection ------------------------------------------
__global__ void k_detect(const int* __restrict__ e32) {
    __shared__ int nonzero;
    if (threadIdx.x == 0) nonzero = 0;
    __syncthreads();
    for (int i = threadIdx.x; i < 1024; i += blockDim.x)
        if (e32[2 * i + 1] != 0) nonzero = 1;
    __syncthreads();
    if (threadIdx.x == 0) g_is64 = (nonzero == 0);
}

// ---------------- graph preprocessing --------------------------------------
__global__ void k_zero_deg() {
    int i = blockIdx.x * blockDim.x + threadIdx.x;
    if (i < N_NODES) g_deg[i] = 0;
}

__global__ void k_hist(const int* __restrict__ e32) {
    int e = blockIdx.x * blockDim.x + threadIdx.x;
    if (e < N_EDGES) {
        int d = edge_at(e32, N_EDGES + e);
        if ((unsigned)d < N_NODES) atomicAdd(&g_deg[d], 1);
    }
}

__global__ void k_scan1() {
    __shared__ int sh[SCAN_B];
    int t = threadIdx.x;
    int i = blockIdx.x * SCAN_B + t;
    int v = (i < N_NODES) ? g_deg[i] : 0;
    sh[t] = v;
    __syncthreads();
    for (int s = 1; s < SCAN_B; s <<= 1) {
        int prev = (t >= s) ? sh[t - s] : 0;
        __syncthreads();
        sh[t] += prev;
        __syncthreads();
    }
    if (i < N_NODES) g_off[i] = sh[t] - v;
    if (t == SCAN_B - 1) g_bsums[blockIdx.x] = sh[t];
}

// parallel exclusive scan over the 98 block sums (was serial 1-thread)
__global__ void k_scan2() {
    __shared__ int sh[128];
    int t = threadIdx.x;
    int v = (t < NB_SCAN) ? g_bsums[t] : 0;
    sh[t] = v;
    __syncthreads();
#pragma unroll
    for (int s = 1; s < 128; s <<= 1) {
        int prev = (t >= s) ? sh[t - s] : 0;
        __syncthreads();
        sh[t] += prev;
        __syncthreads();
    }
    if (t < NB_SCAN) g_bsums[t] = sh[t] - v;   // exclusive
}

__global__ void k_scan3() {
    int i = blockIdx.x * blockDim.x + threadIdx.x;
    if (i < N_NODES) {
        int o = g_off[i] + g_bsums[i >> 10];
        g_off[i] = o;
        g_cursor[i] = o;
        int d = g_deg[i];
        g_invdeg[i] = 1.0f / (float)(d > 1 ? d : 1);
    }
    if (i == 0) g_off[N_NODES] = N_EDGES;
}

__global__ void k_fill_csc(const int* __restrict__ e32) {
    int e = blockIdx.x * blockDim.x + threadIdx.x;
    if (e < N_EDGES) {
        int s = edge_at(e32, e);
        int d = edge_at(e32, N_EDGES + e);
        if ((unsigned)s < N_NODES && (unsigned)d < N_NODES) {
            int p = atomicAdd(&g_cursor[d], 1);
            g_csc[p] = s;
        }
    }
}

// ---------------- weight splitting (per layer, as in R8) --------------------
__global__ void k_split_w(const float* __restrict__ Wl, const float* __restrict__ Wr, int n) {
    int i = blockIdx.x * blockDim.x + threadIdx.x;
    if (i < n) {
        __nv_bfloat16 hi, lo;
        split2(Wl[i], hi, lo); g_Wlhi[i] = hi; g_Wllo[i] = lo;
        split2(Wr[i], hi, lo); g_Wrhi[i] = hi; g_Wrlo[i] = lo;
    }
}

// combined W for layer 2: rows 0..39 = Wl2, rows 40..79 = Wr2 (into g_Wl*)
__global__ void k_split_w2(const float* __restrict__ Wl, const float* __restrict__ Wr) {
    int i = blockIdx.x * blockDim.x + threadIdx.x;
    int n = OUTD_F * DIMF;
    if (i < n) {
        __nv_bfloat16 hi, lo;
        split2(Wl[i], hi, lo); g_Wlhi[i] = hi; g_Wllo[i] = lo;
        split2(Wr[i], hi, lo); g_Wlhi[n + i] = hi; g_Wllo[n + i] = lo;
    }
}

// ---------------- tensor-core GEMM ------------------------------------------
__device__ __forceinline__ void mma_bf16(float* d, const unsigned* a, unsigned b0, unsigned b1) {
    asm volatile(
        "mma.sync.aligned.m16n8k16.row.col.f32.bf16.bf16.f32 "
        "{%0,%1,%2,%3}, {%4,%5,%6,%7}, {%8,%9}, {%0,%1,%2,%3};\n"
        : "+f"(d[0]), "+f"(d[1]), "+f"(d[2]), "+f"(d[3])
        : "r"(a[0]), "r"(a[1]), "r"(a[2]), "r"(a[3]), "r"(b0), "r"(b1));
}

// layers 0/1: blockIdx.y==0 -> U(bf16) = X@Wl^T ; ==1 -> V(f32) = X@Wr^T + b
// FP32A: layer 0 reads harness fp32 x directly and splits into smem.
template <bool FP32A>
__global__ void __launch_bounds__(256) k_gemm_l01(const float* __restrict__ xin,
                                                  const float* __restrict__ bias) {
    constexpr int OUTD = 128;
    constexpr int MT = 2, NT = 8, STR = 20;

    __shared__ __align__(16) unsigned sAh[128 * STR], sAl[128 * STR];
    __shared__ __align__(16) unsigned sWh[OUTD * STR], sWl[OUTD * STR];

    int side = blockIdx.y;
    const unsigned* Ah = (const unsigned*)g_xhi;
    const unsigned* Al = (const unsigned*)g_xlo;
    const unsigned* Wh = (const unsigned*)(side ? g_Wrhi : g_Wlhi);
    const unsigned* Wo = (const unsigned*)(side ? g_Wrlo : g_Wllo);

    int tid  = threadIdx.x;
    int wid  = tid >> 5, lane = tid & 31;
    int mw   = wid & 3, nw = wid >> 2;
    int row0 = blockIdx.x * 128;
    int lg   = lane >> 2, lt = lane & 3;

    float acc[MT][NT][4];
#pragma unroll
    for (int m = 0; m < MT; m++)
#pragma unroll
        for (int n = 0; n < NT; n++)
#pragma unroll
            for (int q = 0; q < 4; q++) acc[m][n][q] = 0.f;

#pragma unroll 1
    for (int kt = 0; kt < 4; kt++) {
        int kw = kt * 16;

        if (FP32A) {
            // read fp32 x, split to bf16 hi/lo while staging to smem
#pragma unroll
            for (int i = tid; i < 1024; i += 256) {
                int r = i >> 3, q = (i & 7) * 4;   // float index within 32-chunk
                float4 v = make_float4(0.f, 0.f, 0.f, 0.f);
                if (row0 + r < N_NODES)
                    v = *(const float4*)(xin + (size_t)(row0 + r) * DIMF + kt * 32 + q);
                unsigned wh0 = bf_pack(v.x, v.y) , wl0, wh1 = bf_pack(v.z, v.w), wl1;
                __nv_bfloat16 h0, l0, h1, l1, h2, l2, h3, l3;
                split2(v.x, h0, l0); split2(v.y, h1, l1);
                split2(v.z, h2, l2); split2(v.w, h3, l3);
                wh0 = ((unsigned)__bfloat16_as_ushort(h1) << 16) | __bfloat16_as_ushort(h0);
                wh1 = ((unsigned)__bfloat16_as_ushort(h3) << 16) | __bfloat16_as_ushort(h2);
                wl0 = ((unsigned)__bfloat16_as_ushort(l1) << 16) | __bfloat16_as_ushort(l0);
                wl1 = ((unsigned)__bfloat16_as_ushort(l3) << 16) | __bfloat16_as_ushort(l2);
                int wq = q >> 1;
                sAh[r * STR + wq] = wh0; sAh[r * STR + wq + 1] = wh1;
                sAl[r * STR + wq] = wl0; sAl[r * STR + wq + 1] = wl1;
            }
        } else {
#pragma unroll
            for (int i = tid; i < 128 * 4; i += 256) {
                int r = i >> 2, q = (i & 3) * 4;
                uint4 vh = make_uint4(0, 0, 0, 0), vl = vh;
                if (row0 + r < N_NODES) {
                    vh = *(const uint4*)(Ah + (size_t)(row0 + r) * 64 + kw + q);
                    vl = *(const uint4*)(Al + (size_t)(row0 + r) * 64 + kw + q);
                }
                *(uint4*)(sAh + r * STR + q) = vh;
                *(uint4*)(sAl + r * STR + q) = vl;
            }
        }
        for (int i = tid; i < OUTD * 4; i += 256) {
            int r = i >> 2, q = (i & 3) * 4;
            *(uint4*)(sWh + r * STR + q) = *(const uint4*)(Wh + (size_t)r * 64 + kw + q);
            *(uint4*)(sWl + r * STR + q) = *(const uint4*)(Wo + (size_t)r * 64 + kw + q);
        }
        __syncthreads();

#pragma unroll
        for (int ks = 0; ks < 2; ks++) {
            int wb = ks * 8;
            unsigned ah[MT][4], al[MT][4];
#pragma unroll
            for (int m = 0; m < MT; m++) {
                int rr = (mw * MT + m) * 16 + lg;
                ah[m][0] = sAh[rr * STR + wb + lt];
                ah[m][1] = sAh[(rr + 8) * STR + wb + lt];
                ah[m][2] = sAh[rr * STR + wb + 4 + lt];
                ah[m][3] = sAh[(rr + 8) * STR + wb + 4 + lt];
                al[m][0] = sAl[rr * STR + wb + lt];
                al[m][1] = sAl[(rr + 8) * STR + wb + lt];
                al[m][2] = sAl[rr * STR + wb + 4 + lt];
                al[m][3] = sAl[(rr + 8) * STR + wb + 4 + lt];
            }
#pragma unroll
            for (int n = 0; n < NT; n++) {
                int nr = nw * NT * 8 + n * 8 + lg;
                unsigned bh0 = sWh[nr * STR + wb + lt];
                unsigned bh1 = sWh[nr * STR + wb + 4 + lt];
                unsigned bl0 = sWl[nr * STR + wb + lt];
                unsigned bl1 = sWl[nr * STR + wb + 4 + lt];
#pragma unroll
                for (int m = 0; m < MT; m++) {
                    mma_bf16(acc[m][n], ah[m], bh0, bh1);
                    mma_bf16(acc[m][n], ah[m], bl0, bl1);
                    mma_bf16(acc[m][n], al[m], bh0, bh1);
                }
            }
        }
        __syncthreads();
    }

#pragma unroll
    for (int m = 0; m < MT; m++) {
        int r = row0 + (mw * MT + m) * 16 + lg;
#pragma unroll
        for (int n = 0; n < NT; n++) {
            int c = nw * NT * 8 + n * 8 + lt * 2;
#pragma unroll
            for (int h = 0; h < 2; h++) {
                int rr = r + h * 8;
                if (rr >= N_NODES) continue;
                float v0 = acc[m][n][h * 2], v1 = acc[m][n][h * 2 + 1];
                if (side) {
                    g_V[(size_t)rr * OUTD + c]     = v0 + bias[c];
                    g_V[(size_t)rr * OUTD + c + 1] = v1 + bias[c + 1];
                } else {
                    *(unsigned*)(g_Ub + (size_t)rr * OUTD + c) = bf_pack(v0, v1);
                }
            }
        }
    }
}

// layer 2: [u|v] = h1 @ [Wl2;Wr2]^T; u -> fp16, v -> f32 + bias
__global__ void __launch_bounds__(256) k_gemm2(const float* __restrict__ bias) {
    constexpr int OUTD = 80;
    constexpr int MT = 2, NT = 5, STR = 20;

    __shared__ __align__(16) unsigned sAh[128 * STR], sAl[128 * STR];
    __shared__ __align__(16) unsigned sWh[OUTD * STR], sWl[OUTD * STR];

    int tid  = threadIdx.x;
    int wid  = tid >> 5, lane = tid & 31;
    int mw   = wid & 3, nw = wid >> 2;
    int row0 = blockIdx.x * 128;
    int lg   = lane >> 2, lt = lane & 3;

    float acc[MT][NT][4];
#pragma unroll
    for (int m = 0; m < MT; m++)
#pragma unroll
        for (int n = 0; n < NT; n++)
#pragma unroll
            for (int q = 0; q < 4; q++) acc[m][n][q] = 0.f;

    const unsigned* Ah = (const unsigned*)g_xhi;
    const unsigned* Al = (const unsigned*)g_xlo;
    const unsigned* Wh = (const unsigned*)g_Wlhi;
    const unsigned* Wo = (const unsigned*)g_Wllo;

#pragma unroll 1
    for (int kt = 0; kt < 4; kt++) {
        int kw = kt * 16;

#pragma unroll
        for (int i = tid; i < 128 * 4; i += 256) {
            int r = i >> 2, q = (i & 3) * 4;
            uint4 vh = make_uint4(0, 0, 0, 0), vl = vh;
            if (row0 + r < N_NODES) {
                vh = *(const uint4*)(Ah + (size_t)(row0 + r) * 64 + kw + q);
                vl = *(const uint4*)(Al + (size_t)(row0 + r) * 64 + kw + q);
            }
            *(uint4*)(sAh + r * STR + q) = vh;
            *(uint4*)(sAl + r * STR + q) = vl;
        }
        for (int i = tid; i < OUTD * 4; i += 256) {
            int r = i >> 2, q = (i & 3) * 4;
            *(uint4*)(sWh + r * STR + q) = *(const uint4*)(Wh + (size_t)r * 64 + kw + q);
            *(uint4*)(sWl + r * STR + q) = *(const uint4*)(Wo + (size_t)r * 64 + kw + q);
        }
        __syncthreads();

#pragma unroll
        for (int ks = 0; ks < 2; ks++) {
            int wb = ks * 8;
            unsigned ah[MT][4], al[MT][4];
#pragma unroll
            for (int m = 0; m < MT; m++) {
                int rr = (mw * MT + m) * 16 + lg;
                ah[m][0] = sAh[rr * STR + wb + lt];
                ah[m][1] = sAh[(rr + 8) * STR + wb + lt];
                ah[m][2] = sAh[rr * STR + wb + 4 + lt];
                ah[m][3] = sAh[(rr + 8) * STR + wb + 4 + lt];
                al[m][0] = sAl[rr * STR + wb + lt];
                al[m][1] = sAl[(rr + 8) * STR + wb + lt];
                al[m][2] = sAl[rr * STR + wb + 4 + lt];
                al[m][3] = sAl[(rr + 8) * STR + wb + 4 + lt];
            }
#pragma unroll
            for (int n = 0; n < NT; n++) {
                int nr = nw * NT * 8 + n * 8 + lg;
                unsigned bh0 = sWh[nr * STR + wb + lt];
                unsigned bh1 = sWh[nr * STR + wb + 4 + lt];
                unsigned bl0 = sWl[nr * STR + wb + lt];
                unsigned bl1 = sWl[nr * STR + wb + 4 + lt];
#pragma unroll
                for (int m = 0; m < MT; m++) {
                    mma_bf16(acc[m][n], ah[m], bh0, bh1);
                    mma_bf16(acc[m][n], ah[m], bl0, bl1);
                    mma_bf16(acc[m][n], al[m], bh0, bh1);
                }
            }
        }
        __syncthreads();
    }

#pragma unroll
    for (int m = 0; m < MT; m++) {
        int r = row0 + (mw * MT + m) * 16 + lg;
#pragma unroll
        for (int n = 0; n < NT; n++) {
            int c = nw * NT * 8 + n * 8 + lt * 2;
#pragma unroll
            for (int h = 0; h < 2; h++) {
                int rr = r + h * 8;
                if (rr >= N_NODES) continue;
                float v0 = acc[m][n][h * 2], v1 = acc[m][n][h * 2 + 1];
                if (c < OUTD_F) {
                    *(__half2*)(g_uh + (size_t)rr * OUTD_F + c) = __floats2half2_rn(v0, v1);
                } else {
                    g_v[(size_t)rr * OUTD_F + c - OUTD_F]     = v0 + bias[c - OUTD_F];
                    g_v[(size_t)rr * OUTD_F + c - OUTD_F + 1] = v1 + bias[c - OUTD_F + 1];
                }
            }
        }
    }
}

// ---------------- fused: gather-mean(U bf16) + V, L2-norm, ReLU, split -----
// one warp per node; lane handles cols [4*lane, 4*lane+3] (uint2 = 4 bf16).
__global__ void k_aggnorm() {
    int warp = (blockIdx.x * blockDim.x + threadIdx.x) >> 5;
    int lane = threadIdx.x & 31;
    if (warp >= N_NODES) return;
    int n = warp;
    const uint2* U2 = (const uint2*)g_Ub;    // row = 32 uint2 (128 bf16)
    int j = g_off[n], je = g_off[n + 1];
    float ax = 0.f, ay = 0.f, az = 0.f, aw = 0.f;
    for (; j + 1 < je; j += 2) {
        int s0 = g_csc[j], s1 = g_csc[j + 1];
        uint2 w0 = U2[(size_t)s0 * 32 + lane];
        uint2 w1 = U2[(size_t)s1 * 32 + lane];
        ax += bf_lo(w0.x) + bf_lo(w1.x);
        ay += bf_hi(w0.x) + bf_hi(w1.x);
        az += bf_lo(w0.y) + bf_lo(w1.y);
        aw += bf_hi(w0.y) + bf_hi(w1.y);
    }
    if (j < je) {
        uint2 w0 = U2[(size_t)g_csc[j] * 32 + lane];
        ax += bf_lo(w0.x); ay += bf_hi(w0.x);
        az += bf_lo(w0.y); aw += bf_hi(w0.y);
    }
    float inv_d = g_invdeg[n];
    float4 vv = ((const float4*)g_V)[(size_t)n * 32 + lane];
    ax = ax * inv_d + vv.x;
    ay = ay * inv_d + vv.y;
    az = az * inv_d + vv.z;
    aw = aw * inv_d + vv.w;

    float ss = ax * ax + ay * ay + az * az + aw * aw;
#pragma unroll
    for (int s = 16; s; s >>= 1) ss += __shfl_xor_sync(0xFFFFFFFFu, ss, s);
    float sc = 1.0f / fmaxf(sqrtf(ss), 1e-12f);
    ax = fmaxf(ax * sc, 0.f);
    ay = fmaxf(ay * sc, 0.f);
    az = fmaxf(az * sc, 0.f);
    aw = fmaxf(aw * sc, 0.f);

    size_t idx = (size_t)n * DIMF + lane * 4;
    __nv_bfloat16 hi, lo;
    split2(ax, hi, lo); g_xhi[idx]     = hi; g_xlo[idx]     = lo;
    split2(ay, hi, lo); g_xhi[idx + 1] = hi; g_xlo[idx + 1] = lo;
    split2(az, hi, lo); g_xhi[idx + 2] = hi; g_xlo[idx + 2] = lo;
    split2(aw, hi, lo); g_xhi[idx + 3] = hi; g_xlo[idx + 3] = lo;
}

// ---------------- layer-2: gather u(fp16), add v, softmax ------------------
__global__ void k_agg_softmax(float* __restrict__ out) {
    int warp = (blockIdx.x * blockDim.x + threadIdx.x) >> 5;
    int lane = threadIdx.x & 31;
    if (warp >= N_NODES) return;
    int n = warp;
    bool act = lane < 20;                    // 2 cols per active lane
    const __half2* u2 = (const __half2*)g_uh;   // row = 20 half2
    int j = g_off[n], je = g_off[n + 1];
    float acc0 = 0.f, acc1 = 0.f;
    for (; j + 1 < je; j += 2) {
        int s0 = g_csc[j], s1 = g_csc[j + 1];
        if (act) {
            float2 f0 = __half22float2(u2[(size_t)s0 * 20 + lane]);
            float2 f1 = __half22float2(u2[(size_t)s1 * 20 + lane]);
            acc0 += f0.x + f1.x;
            acc1 += f0.y + f1.y;
        }
    }
    if (j < je) {
        int s0 = g_csc[j];
        if (act) {
            float2 f0 = __half22float2(u2[(size_t)s0 * 20 + lane]);
            acc0 += f0.x; acc1 += f0.y;
        }
    }
    float inv_d = g_invdeg[n];
    float a0 = -1e30f, a1 = -1e30f;
    if (act) {
        a0 = acc0 * inv_d + g_v[(size_t)n * OUTD_F + lane * 2];
        a1 = acc1 * inv_d + g_v[(size_t)n * OUTD_F + lane * 2 + 1];
    }
    float m = fmaxf(a0, a1);
#pragma unroll
    for (int s = 16; s; s >>= 1) m = fmaxf(m, __shfl_xor_sync(0xFFFFFFFFu, m, s));
    float e0 = act ? __expf(a0 - m) : 0.f;
    float e1 = act ? __expf(a1 - m) : 0.f;
    float sum = e0 + e1;
#pragma unroll
    for (int s = 16; s; s >>= 1) sum += __shfl_xor_sync(0xFFFFFFFFu, sum, s);
    float inv = 1.0f / sum;
    if (act) {
        float* row = out + (size_t)n * OUTD_F + lane * 2;
        row[0] = e0 * inv;
        row[1] = e1 * inv;
    }
}

// ---------------- launch ----------------------------------------------------
extern "C" void kernel_launch(void* const* d_in, const int* in_sizes, int n_in,
                              void* d_out, int out_size) {
    const float* x   = (const float*)d_in[0];
    const int*   e32 = (const int*)d_in[1];
    const float* Wl0 = (const float*)d_in[2];
    const float* Wr0 = (const float*)d_in[3];
    const float* b0  = (const float*)d_in[4];
    const float* Wl1 = (const float*)d_in[5];
    const float* Wr1 = (const float*)d_in[6];
    const float* b1  = (const float*)d_in[7];
    const float* Wl2 = (const float*)d_in[8];
    const float* Wr2 = (const float*)d_in[9];
    const float* b2  = (const float*)d_in[10];
    float* out = (float*)d_out;

    const int TB = 256;
    int nblk_nodes = (N_NODES + TB - 1) / TB;
    int nblk_edges = (N_EDGES + TB - 1) / TB;
    int nblk_gemm  = (N_NODES + 127) / 128;    // 782
    int nblk_wnode = (N_NODES + 7) / 8;        // warp-per-node

    // ---- dtype detect + build CSC ----
    k_detect<<<1, TB>>>(e32);
    k_zero_deg<<<nblk_nodes, TB>>>();
    k_hist<<<nblk_edges, TB>>>(e32);
    k_scan1<<<NB_SCAN, SCAN_B>>>();
    k_scan2<<<1, 128>>>();
    k_scan3<<<nblk_nodes, TB>>>();
    k_fill_csc<<<nblk_edges, TB>>>(e32);

    // ---- layer 0 (fp32 x read directly by GEMM; no split_x pass) ----
    k_split_w<<<(DIMF * DIMF + TB - 1) / TB, TB>>>(Wl0, Wr0, DIMF * DIMF);
    k_gemm_l01<true><<<dim3(nblk_gemm, 2), TB>>>(x, b0);
    k_aggnorm<<<nblk_wnode, TB>>>();

    // ---- layer 1 ----
    k_split_w<<<(DIMF * DIMF + TB - 1) / TB, TB>>>(Wl1, Wr1, DIMF * DIMF);
    k_gemm_l01<false><<<dim3(nblk_gemm, 2), TB>>>(nullptr, b1);
    k_aggnorm<<<nblk_wnode, TB>>>();

    // ---- layer 2 (project-first, fp16 u gather + fused softmax) ----
    k_split_w2<<<(OUTD_F * DIMF + TB - 1) / TB, TB>>>(Wl2, Wr2);
    k_gemm2<<<nblk_gemm, TB>>>(b2);
    k_agg_softmax<<<nblk_wnode, TB>>>(out);
}

// round 11
// speedup vs baseline: 1.8134x; 1.0271x over previous
#include <cuda_runtime.h>
#include <cuda_bf16.h>
#include <cuda_fp16.h>
#include <math.h>

#define N_NODES 100000
#define N_EDGES 1600000
#define DIMF    128
#define OUTD_F  40
#define SCAN_B  1024
#define NB_SCAN 98   // ceil(100000/1024)

// ---------------- scratch (device globals; no allocation allowed) ----------
__device__ int   g_is64;
__device__ int   g_deg[N_NODES];
__device__ float g_invdeg[N_NODES];
__device__ int   g_off[N_NODES + 1];
__device__ int   g_cursor[N_NODES];
__device__ int   g_bsums[NB_SCAN];
__device__ int   g_csc[N_EDGES];
__device__ __align__(16) unsigned short g_Ub[(size_t)N_NODES * DIMF]; // X@Wl^T, bf16 bits
__device__ __align__(16) float  g_V [(size_t)N_NODES * DIMF];          // X@Wr^T + b
__device__ __align__(16) __half g_uh[(size_t)N_NODES * OUTD_F];        // layer2: h1@Wl2^T
__device__ __align__(16) float  g_v [(size_t)N_NODES * OUTD_F];        // layer2: h1@Wr2^T + b2
// bf16 split operands for tensor-core GEMM
__device__ __align__(16) __nv_bfloat16 g_xhi[(size_t)N_NODES * DIMF];
__device__ __align__(16) __nv_bfloat16 g_xlo[(size_t)N_NODES * DIMF];
__device__ __align__(16) __nv_bfloat16 g_Wlhi[DIMF * DIMF], g_Wllo[DIMF * DIMF];
__device__ __align__(16) __nv_bfloat16 g_Wrhi[DIMF * DIMF], g_Wrlo[DIMF * DIMF];

__device__ __forceinline__ int edge_at(const int* __restrict__ e32, int i) {
    return g_is64 ? e32[2 * i] : e32[i];
}
__device__ __forceinline__ void split2(float v, __nv_bfloat16& hi, __nv_bfloat16& lo) {
    hi = __float2bfloat16(v);
    lo = __float2bfloat16(v - __bfloat162float(hi));
}
// bf16-pair unpack via integer ops (no F2F, no register reinterpret)
__device__ __forceinline__ float bf_lo(unsigned w) { return __uint_as_float(w << 16); }
__device__ __forceinline__ float bf_hi(unsigned w) { return __uint_as_float(w & 0xFFFF0000u); }
__device__ __forceinline__ unsigned bf_pack(float a, float b) {
    return (unsigned)__bfloat16_as_ushort(__float2bfloat16(a)) |
           ((unsigned)__bfloat16_as_ushort(__float2bfloat16(b)) << 16);
}

// ---------------- dtype detection ------------------------------------------
__global__ void k_detect(const int* __restrict__ e32) {
    __shared__ int nonzero;
    if (threadIdx.x == 0) nonzero = 0;
    __syncthreads();
    for (int i = threadIdx.x; i < 1024; i += blockDim.x)
        if (e32[2 * i + 1] != 0) nonzero = 1;
    __syncthreads();
    if (threadIdx.x == 0) g_is64 = (nonzero == 0);
}

// ---------------- graph preprocessing --------------------------------------
__global__ void k_zero_deg() {
    int i = blockIdx.x * blockDim.x + threadIdx.x;
    if (i < N_NODES) g_deg[i] = 0;
}

__global__ void k_hist(const int* __restrict__ e32) {
    int e = blockIdx.x * blockDim.x + threadIdx.x;
    if (e < N_EDGES) {
        int d = edge_at(e32, N_EDGES + e);
        if ((unsigned)d < N_NODES) atomicAdd(&g_deg[d], 1);
    }
}

__global__ void k_scan1() {
    __shared__ int sh[SCAN_B];
    int t = threadIdx.x;
    int i = blockIdx.x * SCAN_B + t;
    int v = (i < N_NODES) ? g_deg[i] : 0;
    sh[t] = v;
    __syncthreads();
    for (int s = 1; s < SCAN_B; s <<= 1) {
        int prev = (t >= s) ? sh[t - s] : 0;
        __syncthreads();
        sh[t] += prev;
        __syncthreads();
    }
    if (i < N_NODES) g_off[i] = sh[t] - v;
    if (t == SCAN_B - 1) g_bsums[blockIdx.x] = sh[t];
}

// parallel exclusive scan over the 98 block sums
__global__ void k_scan2() {
    __shared__ int sh[128];
    int t = threadIdx.x;
    int v = (t < NB_SCAN) ? g_bsums[t] : 0;
    sh[t] = v;
    __syncthreads();
#pragma unroll
    for (int s = 1; s < 128; s <<= 1) {
        int prev = (t >= s) ? sh[t - s] : 0;
        __syncthreads();
        sh[t] += prev;
        __syncthreads();
    }
    if (t < NB_SCAN) g_bsums[t] = sh[t] - v;   // exclusive
}

__global__ void k_scan3() {
    int i = blockIdx.x * blockDim.x + threadIdx.x;
    if (i < N_NODES) {
        int o = g_off[i] + g_bsums[i >> 10];
        g_off[i] = o;
        g_cursor[i] = o;
        int d = g_deg[i];
        g_invdeg[i] = 1.0f / (float)(d > 1 ? d : 1);
    }
    if (i == 0) g_off[N_NODES] = N_EDGES;
}

__global__ void k_fill_csc(const int* __restrict__ e32) {
    int e = blockIdx.x * blockDim.x + threadIdx.x;
    if (e < N_EDGES) {
        int s = edge_at(e32, e);
        int d = edge_at(e32, N_EDGES + e);
        if ((unsigned)s < N_NODES && (unsigned)d < N_NODES) {
            int p = atomicAdd(&g_cursor[d], 1);
            g_csc[p] = s;
        }
    }
}

// ---------------- weight splitting ------------------------------------------
__global__ void k_split_w(const float* __restrict__ Wl, const float* __restrict__ Wr, int n) {
    int i = blockIdx.x * blockDim.x + threadIdx.x;
    if (i < n) {
        __nv_bfloat16 hi, lo;
        split2(Wl[i], hi, lo); g_Wlhi[i] = hi; g_Wllo[i] = lo;
        split2(Wr[i], hi, lo); g_Wrhi[i] = hi; g_Wrlo[i] = lo;
    }
}

// combined W for layer 2: rows 0..39 = Wl2, rows 40..79 = Wr2 (into g_Wl*)
__global__ void k_split_w2(const float* __restrict__ Wl, const float* __restrict__ Wr) {
    int i = blockIdx.x * blockDim.x + threadIdx.x;
    int n = OUTD_F * DIMF;
    if (i < n) {
        __nv_bfloat16 hi, lo;
        split2(Wl[i], hi, lo); g_Wlhi[i] = hi; g_Wllo[i] = lo;
        split2(Wr[i], hi, lo); g_Wlhi[n + i] = hi; g_Wllo[n + i] = lo;
    }
}

// ---------------- tensor-core GEMM ------------------------------------------
__device__ __forceinline__ void mma_bf16(float* d, const unsigned* a, unsigned b0, unsigned b1) {
    asm volatile(
        "mma.sync.aligned.m16n8k16.row.col.f32.bf16.bf16.f32 "
        "{%0,%1,%2,%3}, {%4,%5,%6,%7}, {%8,%9}, {%0,%1,%2,%3};\n"
        : "+f"(d[0]), "+f"(d[1]), "+f"(d[2]), "+f"(d[3])
        : "r"(a[0]), "r"(a[1]), "r"(a[2]), "r"(a[3]), "r"(b0), "r"(b1));
}

// layers 0/1: blockIdx.y==0 -> U(bf16) = X@Wl^T ; ==1 -> V(f32) = X@Wr^T + b
// FP32A: layer 0 reads harness fp32 x directly and splits into smem.
template <bool FP32A>
__global__ void __launch_bounds__(256) k_gemm_l01(const float* __restrict__ xin,
                                                  const float* __restrict__ bias) {
    constexpr int OUTD = 128;
    constexpr int MT = 2, NT = 8, STR = 20;

    __shared__ __align__(16) unsigned sAh[128 * STR], sAl[128 * STR];
    __shared__ __align__(16) unsigned sWh[OUTD * STR], sWl[OUTD * STR];

    int side = blockIdx.y;
    const unsigned* Ah = (const unsigned*)g_xhi;
    const unsigned* Al = (const unsigned*)g_xlo;
    const unsigned* Wh = (const unsigned*)(side ? g_Wrhi : g_Wlhi);
    const unsigned* Wo = (const unsigned*)(side ? g_Wrlo : g_Wllo);

    int tid  = threadIdx.x;
    int wid  = tid >> 5, lane = tid & 31;
    int mw   = wid & 3, nw = wid >> 2;
    int row0 = blockIdx.x * 128;
    int lg   = lane >> 2, lt = lane & 3;

    float acc[MT][NT][4];
#pragma unroll
    for (int m = 0; m < MT; m++)
#pragma unroll
        for (int n = 0; n < NT; n++)
#pragma unroll
            for (int q = 0; q < 4; q++) acc[m][n][q] = 0.f;

#pragma unroll 1
    for (int kt = 0; kt < 4; kt++) {
        int kw = kt * 16;

        if (FP32A) {
            // read fp32 x, split to bf16 hi/lo while staging to smem
#pragma unroll
            for (int i = tid; i < 1024; i += 256) {
                int r = i >> 3, q = (i & 7) * 4;   // float index within 32-chunk
                float4 v = make_float4(0.f, 0.f, 0.f, 0.f);
                if (row0 + r < N_NODES)
                    v = *(const float4*)(xin + (size_t)(row0 + r) * DIMF + kt * 32 + q);
                __nv_bfloat16 h0, l0, h1, l1, h2, l2, h3, l3;
                split2(v.x, h0, l0); split2(v.y, h1, l1);
                split2(v.z, h2, l2); split2(v.w, h3, l3);
                unsigned wh0 = ((unsigned)__bfloat16_as_ushort(h1) << 16) | __bfloat16_as_ushort(h0);
                unsigned wh1 = ((unsigned)__bfloat16_as_ushort(h3) << 16) | __bfloat16_as_ushort(h2);
                unsigned wl0 = ((unsigned)__bfloat16_as_ushort(l1) << 16) | __bfloat16_as_ushort(l0);
                unsigned wl1 = ((unsigned)__bfloat16_as_ushort(l3) << 16) | __bfloat16_as_ushort(l2);
                int wq = q >> 1;
                sAh[r * STR + wq] = wh0; sAh[r * STR + wq + 1] = wh1;
                sAl[r * STR + wq] = wl0; sAl[r * STR + wq + 1] = wl1;
            }
        } else {
#pragma unroll
            for (int i = tid; i < 128 * 4; i += 256) {
                int r = i >> 2, q = (i & 3) * 4;
                uint4 vh = make_uint4(0, 0, 0, 0), vl = vh;
                if (row0 + r < N_NODES) {
                    vh = *(const uint4*)(Ah + (size_t)(row0 + r) * 64 + kw + q);
                    vl = *(const uint4*)(Al + (size_t)(row0 + r) * 64 + kw + q);
                }
                *(uint4*)(sAh + r * STR + q) = vh;
                *(uint4*)(sAl + r * STR + q) = vl;
            }
        }
        for (int i = tid; i < OUTD * 4; i += 256) {
            int r = i >> 2, q = (i & 3) * 4;
            *(uint4*)(sWh + r * STR + q) = *(const uint4*)(Wh + (size_t)r * 64 + kw + q);
            *(uint4*)(sWl + r * STR + q) = *(const uint4*)(Wo + (size_t)r * 64 + kw + q);
        }
        __syncthreads();

#pragma unroll
        for (int ks = 0; ks < 2; ks++) {
            int wb = ks * 8;
            unsigned ah[MT][4], al[MT][4];
#pragma unroll
            for (int m = 0; m < MT; m++) {
                int rr = (mw * MT + m) * 16 + lg;
                ah[m][0] = sAh[rr * STR + wb + lt];
                ah[m][1] = sAh[(rr + 8) * STR + wb + lt];
                ah[m][2] = sAh[rr * STR + wb + 4 + lt];
                ah[m][3] = sAh[(rr + 8) * STR + wb + 4 + lt];
                al[m][0] = sAl[rr * STR + wb + lt];
                al[m][1] = sAl[(rr + 8) * STR + wb + lt];
                al[m][2] = sAl[rr * STR + wb + 4 + lt];
                al[m][3] = sAl[(rr + 8) * STR + wb + 4 + lt];
            }
#pragma unroll
            for (int n = 0; n < NT; n++) {
                int nr = nw * NT * 8 + n * 8 + lg;
                unsigned bh0 = sWh[nr * STR + wb + lt];
                unsigned bh1 = sWh[nr * STR + wb + 4 + lt];
                unsigned bl0 = sWl[nr * STR + wb + lt];
                unsigned bl1 = sWl[nr * STR + wb + 4 + lt];
#pragma unroll
                for (int m = 0; m < MT; m++) {
                    mma_bf16(acc[m][n], ah[m], bh0, bh1);
                    mma_bf16(acc[m][n], ah[m], bl0, bl1);
                    mma_bf16(acc[m][n], al[m], bh0, bh1);
                }
            }
        }
        __syncthreads();
    }

#pragma unroll
    for (int m = 0; m < MT; m++) {
        int r = row0 + (mw * MT + m) * 16 + lg;
#pragma unroll
        for (int n = 0; n < NT; n++) {
            int c = nw * NT * 8 + n * 8 + lt * 2;
#pragma unroll
            for (int h = 0; h < 2; h++) {
                int rr = r + h * 8;
                if (rr >= N_NODES) continue;
                float v0 = acc[m][n][h * 2], v1 = acc[m][n][h * 2 + 1];
                if (side) {
                    g_V[(size_t)rr * OUTD + c]     = v0 + bias[c];
                    g_V[(size_t)rr * OUTD + c + 1] = v1 + bias[c + 1];
                } else {
                    *(unsigned*)(g_Ub + (size_t)rr * OUTD + c) = bf_pack(v0, v1);
                }
            }
        }
    }
}

// layer 2: [u|v] = h1 @ [Wl2;Wr2]^T; u -> fp16, v -> f32 + bias
__global__ void __launch_bounds__(256) k_gemm2(const float* __restrict__ bias) {
    constexpr int OUTD = 80;
    constexpr int MT = 2, NT = 5, STR = 20;

    __shared__ __align__(16) unsigned sAh[128 * STR], sAl[128 * STR];
    __shared__ __align__(16) unsigned sWh[OUTD * STR], sWl[OUTD * STR];

    int tid  = threadIdx.x;
    int wid  = tid >> 5, lane = tid & 31;
    int mw   = wid & 3, nw = wid >> 2;
    int row0 = blockIdx.x * 128;
    int lg   = lane >> 2, lt = lane & 3;

    float acc[MT][NT][4];
#pragma unroll
    for (int m = 0; m < MT; m++)
#pragma unroll
        for (int n = 0; n < NT; n++)
#pragma unroll
            for (int q = 0; q < 4; q++) acc[m][n][q] = 0.f;

    const unsigned* Ah = (const unsigned*)g_xhi;
    const unsigned* Al = (const unsigned*)g_xlo;
    const unsigned* Wh = (const unsigned*)g_Wlhi;
    const unsigned* Wo = (const unsigned*)g_Wllo;

#pragma unroll 1
    for (int kt = 0; kt < 4; kt++) {
        int kw = kt * 16;

#pragma unroll
        for (int i = tid; i < 128 * 4; i += 256) {
            int r = i >> 2, q = (i & 3) * 4;
            uint4 vh = make_uint4(0, 0, 0, 0), vl = vh;
            if (row0 + r < N_NODES) {
                vh = *(const uint4*)(Ah + (size_t)(row0 + r) * 64 + kw + q);
                vl = *(const uint4*)(Al + (size_t)(row0 + r) * 64 + kw + q);
            }
            *(uint4*)(sAh + r * STR + q) = vh;
            *(uint4*)(sAl + r * STR + q) = vl;
        }
        for (int i = tid; i < OUTD * 4; i += 256) {
            int r = i >> 2, q = (i & 3) * 4;
            *(uint4*)(sWh + r * STR + q) = *(const uint4*)(Wh + (size_t)r * 64 + kw + q);
            *(uint4*)(sWl + r * STR + q) = *(const uint4*)(Wo + (size_t)r * 64 + kw + q);
        }
        __syncthreads();

#pragma unroll
        for (int ks = 0; ks < 2; ks++) {
            int wb = ks * 8;
            unsigned ah[MT][4], al[MT][4];
#pragma unroll
            for (int m = 0; m < MT; m++) {
                int rr = (mw * MT + m) * 16 + lg;
                ah[m][0] = sAh[rr * STR + wb + lt];
                ah[m][1] = sAh[(rr + 8) * STR + wb + lt];
                ah[m][2] = sAh[rr * STR + wb + 4 + lt];
                ah[m][3] = sAh[(rr + 8) * STR + wb + 4 + lt];
                al[m][0] = sAl[rr * STR + wb + lt];
                al[m][1] = sAl[(rr + 8) * STR + wb + lt];
                al[m][2] = sAl[rr * STR + wb + 4 + lt];
                al[m][3] = sAl[(rr + 8) * STR + wb + 4 + lt];
            }
#pragma unroll
            for (int n = 0; n < NT; n++) {
                int nr = nw * NT * 8 + n * 8 + lg;
                unsigned bh0 = sWh[nr * STR + wb + lt];
                unsigned bh1 = sWh[nr * STR + wb + 4 + lt];
                unsigned bl0 = sWl[nr * STR + wb + lt];
                unsigned bl1 = sWl[nr * STR + wb + 4 + lt];
#pragma unroll
                for (int m = 0; m < MT; m++) {
                    mma_bf16(acc[m][n], ah[m], bh0, bh1);
                    mma_bf16(acc[m][n], ah[m], bl0, bl1);
                    mma_bf16(acc[m][n], al[m], bh0, bh1);
                }
            }
        }
        __syncthreads();
    }

#pragma unroll
    for (int m = 0; m < MT; m++) {
        int r = row0 + (mw * MT + m) * 16 + lg;
#pragma unroll
        for (int n = 0; n < NT; n++) {
            int c = nw * NT * 8 + n * 8 + lt * 2;
#pragma unroll
            for (int h = 0; h < 2; h++) {
                int rr = r + h * 8;
                if (rr >= N_NODES) continue;
                float v0 = acc[m][n][h * 2], v1 = acc[m][n][h * 2 + 1];
                if (c < OUTD_F) {
                    *(__half2*)(g_uh + (size_t)rr * OUTD_F + c) = __floats2half2_rn(v0, v1);
                } else {
                    g_v[(size_t)rr * OUTD_F + c - OUTD_F]     = v0 + bias[c - OUTD_F];
                    g_v[(size_t)rr * OUTD_F + c - OUTD_F + 1] = v1 + bias[c - OUTD_F + 1];
                }
            }
        }
    }
}

// ---------------- fused: gather-mean(U bf16) + V, L2-norm, ReLU, split -----
// one warp per node; lane handles cols [4*lane, 4*lane+3].
// Software-pipelined: next group's csc indices load while current rows in flight.
__global__ void k_aggnorm() {
    int warp = (blockIdx.x * blockDim.x + threadIdx.x) >> 5;
    int lane = threadIdx.x & 31;
    if (warp >= N_NODES) return;
    int n = warp;
    const uint2* __restrict__ U2 = (const uint2*)g_Ub;   // row = 32 uint2 (128 bf16)
    const int* __restrict__ csc = g_csc;
    int j = g_off[n], je = g_off[n + 1];
    float ax = 0.f, ay = 0.f, az = 0.f, aw = 0.f;

    int s0 = 0, s1 = 0, s2 = 0, s3 = 0;
    if (j + 3 < je) {
        s0 = __ldg(&csc[j]);     s1 = __ldg(&csc[j + 1]);
        s2 = __ldg(&csc[j + 2]); s3 = __ldg(&csc[j + 3]);
    }
    while (j + 3 < je) {
        // issue current group's row loads (4 independent)
        uint2 w0 = __ldg(&U2[(size_t)s0 * 32 + lane]);
        uint2 w1 = __ldg(&U2[(size_t)s1 * 32 + lane]);
        uint2 w2 = __ldg(&U2[(size_t)s2 * 32 + lane]);
        uint2 w3 = __ldg(&U2[(size_t)s3 * 32 + lane]);
        int jn = j + 4;
        // prefetch next indices while rows are in flight
        if (jn + 3 < je) {
            s0 = __ldg(&csc[jn]);     s1 = __ldg(&csc[jn + 1]);
            s2 = __ldg(&csc[jn + 2]); s3 = __ldg(&csc[jn + 3]);
        }
        ax += bf_lo(w0.x) + bf_lo(w1.x) + bf_lo(w2.x) + bf_lo(w3.x);
        ay += bf_hi(w0.x) + bf_hi(w1.x) + bf_hi(w2.x) + bf_hi(w3.x);
        az += bf_lo(w0.y) + bf_lo(w1.y) + bf_lo(w2.y) + bf_lo(w3.y);
        aw += bf_hi(w0.y) + bf_hi(w1.y) + bf_hi(w2.y) + bf_hi(w3.y);
        j = jn;
    }
    for (; j < je; j++) {
        uint2 w0 = __ldg(&U2[(size_t)__ldg(&csc[j]) * 32 + lane]);
        ax += bf_lo(w0.x); ay += bf_hi(w0.x);
        az += bf_lo(w0.y); aw += bf_hi(w0.y);
    }
    float inv_d = g_invdeg[n];
    float4 vv = ((const float4*)g_V)[(size_t)n * 32 + lane];
    ax = ax * inv_d + vv.x;
    ay = ay * inv_d + vv.y;
    az = az * inv_d + vv.z;
    aw = aw * inv_d + vv.w;

    float ss = ax * ax + ay * ay + az * az + aw * aw;
#pragma unroll
    for (int s = 16; s; s >>= 1) ss += __shfl_xor_sync(0xFFFFFFFFu, ss, s);
    float sc = 1.0f / fmaxf(sqrtf(ss), 1e-12f);
    ax = fmaxf(ax * sc, 0.f);
    ay = fmaxf(ay * sc, 0.f);
    az = fmaxf(az * sc, 0.f);
    aw = fmaxf(aw * sc, 0.f);

    size_t idx = (size_t)n * DIMF + lane * 4;
    __nv_bfloat16 hi, lo;
    split2(ax, hi, lo); g_xhi[idx]     = hi; g_xlo[idx]     = lo;
    split2(ay, hi, lo); g_xhi[idx + 1] = hi; g_xlo[idx + 1] = lo;
    split2(az, hi, lo); g_xhi[idx + 2] = hi; g_xlo[idx + 2] = lo;
    split2(aw, hi, lo); g_xhi[idx + 3] = hi; g_xlo[idx + 3] = lo;
}

// ---------------- layer-2: gather u(fp16), add v, softmax ------------------
// same pipelined index prefetch.
__global__ void k_agg_softmax(float* __restrict__ out) {
    int warp = (blockIdx.x * blockDim.x + threadIdx.x) >> 5;
    int lane = threadIdx.x & 31;
    if (warp >= N_NODES) return;
    int n = warp;
    bool act = lane < 20;                        // 2 cols per active lane
    const __half2* __restrict__ u2 = (const __half2*)g_uh;   // row = 20 half2
    const int* __restrict__ csc = g_csc;
    int j = g_off[n], je = g_off[n + 1];
    float acc0 = 0.f, acc1 = 0.f;

    int s0 = 0, s1 = 0, s2 = 0, s3 = 0;
    if (j + 3 < je) {
        s0 = __ldg(&csc[j]);     s1 = __ldg(&csc[j + 1]);
        s2 = __ldg(&csc[j + 2]); s3 = __ldg(&csc[j + 3]);
    }
    while (j + 3 < je) {
        float2 f0, f1, f2, f3;
        if (act) {
            f0 = __half22float2(__ldg(&u2[(size_t)s0 * 20 + lane]));
            f1 = __half22float2(__ldg(&u2[(size_t)s1 * 20 + lane]));
            f2 = __half22float2(__ldg(&u2[(size_t)s2 * 20 + lane]));
            f3 = __half22float2(__ldg(&u2[(size_t)s3 * 20 + lane]));
        }
        int jn = j + 4;
        if (jn + 3 < je) {
            s0 = __ldg(&csc[jn]);     s1 = __ldg(&csc[jn + 1]);
            s2 = __ldg(&csc[jn + 2]); s3 = __ldg(&csc[jn + 3]);
        }
        if (act) {
            acc0 += f0.x + f1.x + f2.x + f3.x;
            acc1 += f0.y + f1.y + f2.y + f3.y;
        }
        j = jn;
    }
    for (; j < je; j++) {
        int s = __ldg(&csc[j]);
        if (act) {
            float2 f0 = __half22float2(__ldg(&u2[(size_t)s * 20 + lane]));
            acc0 += f0.x; acc1 += f0.y;
        }
    }
    float inv_d = g_invdeg[n];
    float a0 = -1e30f, a1 = -1e30f;
    if (act) {
        a0 = acc0 * inv_d + g_v[(size_t)n * OUTD_F + lane * 2];
        a1 = acc1 * inv_d + g_v[(size_t)n * OUTD_F + lane * 2 + 1];
    }
    float m = fmaxf(a0, a1);
#pragma unroll
    for (int s = 16; s; s >>= 1) m = fmaxf(m, __shfl_xor_sync(0xFFFFFFFFu, m, s));
    float e0 = act ? __expf(a0 - m) : 0.f;
    float e1 = act ? __expf(a1 - m) : 0.f;
    float sum = e0 + e1;
#pragma unroll
    for (int s = 16; s; s >>= 1) sum += __shfl_xor_sync(0xFFFFFFFFu, sum, s);
    float inv = 1.0f / sum;
    if (act) {
        float* row = out + (size_t)n * OUTD_F + lane * 2;
        row[0] = e0 * inv;
        row[1] = e1 * inv;
    }
}

// ---------------- launch ----------------------------------------------------
extern "C" void kernel_launch(void* const* d_in, const int* in_sizes, int n_in,
                              void* d_out, int out_size) {
    const float* x   = (const float*)d_in[0];
    const int*   e32 = (const int*)d_in[1];
    const float* Wl0 = (const float*)d_in[2];
    const float* Wr0 = (const float*)d_in[3];
    const float* b0  = (const float*)d_in[4];
    const float* Wl1 = (const float*)d_in[5];
    const float* Wr1 = (const float*)d_in[6];
    const float* b1  = (const float*)d_in[7];
    const float* Wl2 = (const float*)d_in[8];
    const float* Wr2 = (const float*)d_in[9];
    const float* b2  = (const float*)d_in[10];
    float* out = (float*)d_out;

    const int TB = 256;
    int nblk_nodes = (N_NODES + TB - 1) / TB;
    int nblk_edges = (N_EDGES + TB - 1) / TB;
    int nblk_gemm  = (N_NODES + 127) / 128;    // 782
    int nblk_wnode = (N_NODES + 7) / 8;        // warp-per-node

    // ---- dtype detect + build CSC ----
    k_detect<<<1, TB>>>(e32);
    k_zero_deg<<<nblk_nodes, TB>>>();
    k_hist<<<nblk_edges, TB>>>(e32);
    k_scan1<<<NB_SCAN, SCAN_B>>>();
    k_scan2<<<1, 128>>>();
    k_scan3<<<nblk_nodes, TB>>>();
    k_fill_csc<<<nblk_edges, TB>>>(e32);

    // ---- layer 0 (fp32 x read directly by GEMM) ----
    k_split_w<<<(DIMF * DIMF + TB - 1) / TB, TB>>>(Wl0, Wr0, DIMF * DIMF);
    k_gemm_l01<true><<<dim3(nblk_gemm, 2), TB>>>(x, b0);
    k_aggnorm<<<nblk_wnode, TB>>>();

    // ---- layer 1 ----
    k_split_w<<<(DIMF * DIMF + TB - 1) / TB, TB>>>(Wl1, Wr1, DIMF * DIMF);
    k_gemm_l01<false><<<dim3(nblk_gemm, 2), TB>>>(nullptr, b1);
    k_aggnorm<<<nblk_wnode, TB>>>();

    // ---- layer 2 (project-first, fp16 u gather + fused softmax) ----
    k_split_w2<<<(OUTD_F * DIMF + TB - 1) / TB, TB>>>(Wl2, Wr2);
    k_gemm2<<<nblk_gemm, TB>>>(b2);
    k_agg_softmax<<<nblk_wnode, TB>>>(out);
}

// round 13
// speedup vs baseline: 1.8962x; 1.0457x over previous
#include <cuda_runtime.h>
#include <cuda_bf16.h>
#include <cuda_fp16.h>
#include <math.h>

#define N_NODES 100000
#define N_EDGES 1600000
#define DIMF    128
#define OUTD_F  40
#define SCAN_B  1024
#define NB_SCAN 98   // ceil(100000/1024)

// ---------------- scratch (device globals; no allocation allowed) ----------
__device__ int   g_is64;
__device__ int   g_deg[N_NODES];
__device__ float g_invdeg[N_NODES];
__device__ int   g_off[N_NODES + 1];
__device__ int   g_cursor[N_NODES];
__device__ int   g_bsums[NB_SCAN];
__device__ int   g_csc[N_EDGES];
__device__ __align__(16) unsigned short g_Ub[(size_t)N_NODES * DIMF]; // X@Wl^T, bf16 bits
__device__ __align__(16) float  g_V [(size_t)N_NODES * DIMF];          // X@Wr^T + b
__device__ __align__(16) __half g_uh[(size_t)N_NODES * OUTD_F];        // layer2: h1@Wl2^T
__device__ __align__(16) float  g_v [(size_t)N_NODES * OUTD_F];        // layer2: h1@Wr2^T + b2
// activations: single bf16 copy (A operand); weights: bf16 hi/lo split
__device__ __align__(16) __nv_bfloat16 g_xhi[(size_t)N_NODES * DIMF];
__device__ __align__(16) __nv_bfloat16 g_Wlhi[DIMF * DIMF], g_Wllo[DIMF * DIMF];
__device__ __align__(16) __nv_bfloat16 g_Wrhi[DIMF * DIMF], g_Wrlo[DIMF * DIMF];

__device__ __forceinline__ int edge_at(const int* __restrict__ e32, int i) {
    return g_is64 ? e32[2 * i] : e32[i];
}
__device__ __forceinline__ void split2(float v, __nv_bfloat16& hi, __nv_bfloat16& lo) {
    hi = __float2bfloat16(v);
    lo = __float2bfloat16(v - __bfloat162float(hi));
}
// bf16-pair unpack via integer ops
__device__ __forceinline__ float bf_lo(unsigned w) { return __uint_as_float(w << 16); }
__device__ __forceinline__ float bf_hi(unsigned w) { return __uint_as_float(w & 0xFFFF0000u); }
__device__ __forceinline__ unsigned bf_pack(float a, float b) {
    return (unsigned)__bfloat16_as_ushort(__float2bfloat16(a)) |
           ((unsigned)__bfloat16_as_ushort(__float2bfloat16(b)) << 16);
}

// ---------------- dtype detection ------------------------------------------
__global__ void k_detect(const int* __restrict__ e32) {
    __shared__ int nonzero;
    if (threadIdx.x == 0) nonzero = 0;
    __syncthreads();
    for (int i = threadIdx.x; i < 1024; i += blockDim.x)
        if (e32[2 * i + 1] != 0) nonzero = 1;
    __syncthreads();
    if (threadIdx.x == 0) g_is64 = (nonzero == 0);
}

// ---------------- graph preprocessing --------------------------------------
__global__ void k_zero_deg() {
    int i = blockIdx.x * blockDim.x + threadIdx.x;
    if (i < N_NODES) g_deg[i] = 0;
}

__global__ void k_hist(const int* __restrict__ e32) {
    int e = blockIdx.x * blockDim.x + threadIdx.x;
    if (e < N_EDGES) {
        int d = edge_at(e32, N_EDGES + e);
        if ((unsigned)d < N_NODES) atomicAdd(&g_deg[d], 1);
    }
}

__global__ void k_scan1() {
    __shared__ int sh[SCAN_B];
    int t = threadIdx.x;
    int i = blockIdx.x * SCAN_B + t;
    int v = (i < N_NODES) ? g_deg[i] : 0;
    sh[t] = v;
    __syncthreads();
    for (int s = 1; s < SCAN_B; s <<= 1) {
        int prev = (t >= s) ? sh[t - s] : 0;
        __syncthreads();
        sh[t] += prev;
        __syncthreads();
    }
    if (i < N_NODES) g_off[i] = sh[t] - v;
    if (t == SCAN_B - 1) g_bsums[blockIdx.x] = sh[t];
}

__global__ void k_scan2() {
    __shared__ int sh[128];
    int t = threadIdx.x;
    int v = (t < NB_SCAN) ? g_bsums[t] : 0;
    sh[t] = v;
    __syncthreads();
#pragma unroll
    for (int s = 1; s < 128; s <<= 1) {
        int prev = (t >= s) ? sh[t - s] : 0;
        __syncthreads();
        sh[t] += prev;
        __syncthreads();
    }
    if (t < NB_SCAN) g_bsums[t] = sh[t] - v;   // exclusive
}

__global__ void k_scan3() {
    int i = blockIdx.x * blockDim.x + threadIdx.x;
    if (i < N_NODES) {
        int o = g_off[i] + g_bsums[i >> 10];
        g_off[i] = o;
        g_cursor[i] = o;
        int d = g_deg[i];
        g_invdeg[i] = 1.0f / (float)(d > 1 ? d : 1);
    }
    if (i == 0) g_off[N_NODES] = N_EDGES;
}

__global__ void k_fill_csc(const int* __restrict__ e32) {
    int e = blockIdx.x * blockDim.x + threadIdx.x;
    if (e < N_EDGES) {
        int s = edge_at(e32, e);
        int d = edge_at(e32, N_EDGES + e);
        if ((unsigned)s < N_NODES && (unsigned)d < N_NODES) {
            int p = atomicAdd(&g_cursor[d], 1);
            g_csc[p] = s;
        }
    }
}

// ---------------- weight splitting (hi/lo kept for weights) ----------------
__global__ void k_split_w(const float* __restrict__ Wl, const float* __restrict__ Wr, int n) {
    int i = blockIdx.x * blockDim.x + threadIdx.x;
    if (i < n) {
        __nv_bfloat16 hi, lo;
        split2(Wl[i], hi, lo); g_Wlhi[i] = hi; g_Wllo[i] = lo;
        split2(Wr[i], hi, lo); g_Wrhi[i] = hi; g_Wrlo[i] = lo;
    }
}

__global__ void k_split_w2(const float* __restrict__ Wl, const float* __restrict__ Wr) {
    int i = blockIdx.x * blockDim.x + threadIdx.x;
    int n = OUTD_F * DIMF;
    if (i < n) {
        __nv_bfloat16 hi, lo;
        split2(Wl[i], hi, lo); g_Wlhi[i] = hi; g_Wllo[i] = lo;
        split2(Wr[i], hi, lo); g_Wlhi[n + i] = hi; g_Wllo[n + i] = lo;
    }
}

// ---------------- tensor-core GEMM ------------------------------------------
__device__ __forceinline__ void mma_bf16(float* d, const unsigned* a, unsigned b0, unsigned b1) {
    asm volatile(
        "mma.sync.aligned.m16n8k16.row.col.f32.bf16.bf16.f32 "
        "{%0,%1,%2,%3}, {%4,%5,%6,%7}, {%8,%9}, {%0,%1,%2,%3};\n"
        : "+f"(d[0]), "+f"(d[1]), "+f"(d[2]), "+f"(d[3])
        : "r"(a[0]), "r"(a[1]), "r"(a[2]), "r"(a[3]), "r"(b0), "r"(b1));
}

// layers 0/1: blockIdx.y==0 -> U(bf16) = X@Wl^T ; ==1 -> V(f32) = X@Wr^T + b
// bf16x2: D = A_bf16 * (W_hi + W_lo). FP32A: layer 0 reads fp32 x directly.
template <bool FP32A>
__global__ void __launch_bounds__(256) k_gemm_l01(const float* __restrict__ xin,
                                                  const float* __restrict__ bias) {
    constexpr int OUTD = 128;
    constexpr int MT = 2, NT = 8, STR = 20;

    __shared__ __align__(16) unsigned sAh[128 * STR];
    __shared__ __align__(16) unsigned sWh[OUTD * STR], sWl[OUTD * STR];

    int side = blockIdx.y;
    const unsigned* Ah = (const unsigned*)g_xhi;
    const unsigned* Wh = (const unsigned*)(side ? g_Wrhi : g_Wlhi);
    const unsigned* Wo = (const unsigned*)(side ? g_Wrlo : g_Wllo);

    int tid  = threadIdx.x;
    int wid  = tid >> 5, lane = tid & 31;
    int mw   = wid & 3, nw = wid >> 2;
    int row0 = blockIdx.x * 128;
    int lg   = lane >> 2, lt = lane & 3;

    float acc[MT][NT][4];
#pragma unroll
    for (int m = 0; m < MT; m++)
#pragma unroll
        for (int n = 0; n < NT; n++)
#pragma unroll
            for (int q = 0; q < 4; q++) acc[m][n][q] = 0.f;

#pragma unroll 1
    for (int kt = 0; kt < 4; kt++) {
        int kw = kt * 16;

        if (FP32A) {
            // read fp32 x, round to bf16 while staging to smem
#pragma unroll
            for (int i = tid; i < 1024; i += 256) {
                int r = i >> 3, q = (i & 7) * 4;   // float index within 32-chunk
                float4 v = make_float4(0.f, 0.f, 0.f, 0.f);
                if (row0 + r < N_NODES)
                    v = *(const float4*)(xin + (size_t)(row0 + r) * DIMF + kt * 32 + q);
                int wq = q >> 1;
                sAh[r * STR + wq]     = bf_pack(v.x, v.y);
                sAh[r * STR + wq + 1] = bf_pack(v.z, v.w);
            }
        } else {
            // bf16 A tile: 128 rows x 16 words = 512 uint4, 2 per thread
#pragma unroll
            for (int i = tid; i < 128 * 4; i += 256) {
                int r = i >> 2, q = (i & 3) * 4;
                uint4 vh = make_uint4(0, 0, 0, 0);
                if (row0 + r < N_NODES)
                    vh = *(const uint4*)(Ah + (size_t)(row0 + r) * 64 + kw + q);
                *(uint4*)(sAh + r * STR + q) = vh;
            }
        }
        for (int i = tid; i < OUTD * 4; i += 256) {
            int r = i >> 2, q = (i & 3) * 4;
            *(uint4*)(sWh + r * STR + q) = *(const uint4*)(Wh + (size_t)r * 64 + kw + q);
            *(uint4*)(sWl + r * STR + q) = *(const uint4*)(Wo + (size_t)r * 64 + kw + q);
        }
        __syncthreads();

#pragma unroll
        for (int ks = 0; ks < 2; ks++) {
            int wb = ks * 8;
            unsigned ah[MT][4];
#pragma unroll
            for (int m = 0; m < MT; m++) {
                int rr = (mw * MT + m) * 16 + lg;
                ah[m][0] = sAh[rr * STR + wb + lt];
                ah[m][1] = sAh[(rr + 8) * STR + wb + lt];
                ah[m][2] = sAh[rr * STR + wb + 4 + lt];
                ah[m][3] = sAh[(rr + 8) * STR + wb + 4 + lt];
            }
#pragma unroll
            for (int n = 0; n < NT; n++) {
                int nr = nw * NT * 8 + n * 8 + lg;
                unsigned bh0 = sWh[nr * STR + wb + lt];
                unsigned bh1 = sWh[nr * STR + wb + 4 + lt];
                unsigned bl0 = sWl[nr * STR + wb + lt];
                unsigned bl1 = sWl[nr * STR + wb + 4 + lt];
#pragma unroll
                for (int m = 0; m < MT; m++) {
                    mma_bf16(acc[m][n], ah[m], bh0, bh1);
                    mma_bf16(acc[m][n], ah[m], bl0, bl1);
                }
            }
        }
        __syncthreads();
    }

#pragma unroll
    for (int m = 0; m < MT; m++) {
        int r = row0 + (mw * MT + m) * 16 + lg;
#pragma unroll
        for (int n = 0; n < NT; n++) {
            int c = nw * NT * 8 + n * 8 + lt * 2;
#pragma unroll
            for (int h = 0; h < 2; h++) {
                int rr = r + h * 8;
                if (rr >= N_NODES) continue;
                float v0 = acc[m][n][h * 2], v1 = acc[m][n][h * 2 + 1];
                if (side) {
                    g_V[(size_t)rr * OUTD + c]     = v0 + bias[c];
                    g_V[(size_t)rr * OUTD + c + 1] = v1 + bias[c + 1];
                } else {
                    *(unsigned*)(g_Ub + (size_t)rr * OUTD + c) = bf_pack(v0, v1);
                }
            }
        }
    }
}

// layer 2: [u|v] = h1 @ [Wl2;Wr2]^T; u -> fp16, v -> f32 + bias. bf16x2.
__global__ void __launch_bounds__(256) k_gemm2(const float* __restrict__ bias) {
    constexpr int OUTD = 80;
    constexpr int MT = 2, NT = 5, STR = 20;

    __shared__ __align__(16) unsigned sAh[128 * STR];
    __shared__ __align__(16) unsigned sWh[OUTD * STR], sWl[OUTD * STR];

    int tid  = threadIdx.x;
    int wid  = tid >> 5, lane = tid & 31;
    int mw   = wid & 3, nw = wid >> 2;
    int row0 = blockIdx.x * 128;
    int lg   = lane >> 2, lt = lane & 3;

    float acc[MT][NT][4];
#pragma unroll
    for (int m = 0; m < MT; m++)
#pragma unroll
        for (int n = 0; n < NT; n++)
#pragma unroll
            for (int q = 0; q < 4; q++) acc[m][n][q] = 0.f;

    const unsigned* Ah = (const unsigned*)g_xhi;
    const unsigned* Wh = (const unsigned*)g_Wlhi;
    const unsigned* Wo = (const unsigned*)g_Wllo;

#pragma unroll 1
    for (int kt = 0; kt < 4; kt++) {
        int kw = kt * 16;

#pragma unroll
        for (int i = tid; i < 128 * 4; i += 256) {
            int r = i >> 2, q = (i & 3) * 4;
            uint4 vh = make_uint4(0, 0, 0, 0);
            if (row0 + r < N_NODES)
                vh = *(const uint4*)(Ah + (size_t)(row0 + r) * 64 + kw + q);
            *(uint4*)(sAh + r * STR + q) = vh;
        }
        for (int i = tid; i < OUTD * 4; i += 256) {
            int r = i >> 2, q = (i & 3) * 4;
            *(uint4*)(sWh + r * STR + q) = *(const uint4*)(Wh + (size_t)r * 64 + kw + q);
            *(uint4*)(sWl + r * STR + q) = *(const uint4*)(Wo + (size_t)r * 64 + kw + q);
        }
        __syncthreads();

#pragma unroll
        for (int ks = 0; ks < 2; ks++) {
            int wb = ks * 8;
            unsigned ah[MT][4];
#pragma unroll
            for (int m = 0; m < MT; m++) {
                int rr = (mw * MT + m) * 16 + lg;
                ah[m][0] = sAh[rr * STR + wb + lt];
                ah[m][1] = sAh[(rr + 8) * STR + wb + lt];
                ah[m][2] = sAh[rr * STR + wb + 4 + lt];
                ah[m][3] = sAh[(rr + 8) * STR + wb + 4 + lt];
            }
#pragma unroll
            for (int n = 0; n < NT; n++) {
                int nr = nw * NT * 8 + n * 8 + lg;
                unsigned bh0 = sWh[nr * STR + wb + lt];
                unsigned bh1 = sWh[nr * STR + wb + 4 + lt];
                unsigned bl0 = sWl[nr * STR + wb + lt];
                unsigned bl1 = sWl[nr * STR + wb + 4 + lt];
#pragma unroll
                for (int m = 0; m < MT; m++) {
                    mma_bf16(acc[m][n], ah[m], bh0, bh1);
                    mma_bf16(acc[m][n], ah[m], bl0, bl1);
                }
            }
        }
        __syncthreads();
    }

#pragma unroll
    for (int m = 0; m < MT; m++) {
        int r = row0 + (mw * MT + m) * 16 + lg;
#pragma unroll
        for (int n = 0; n < NT; n++) {
            int c = nw * NT * 8 + n * 8 + lt * 2;
#pragma unroll
            for (int h = 0; h < 2; h++) {
                int rr = r + h * 8;
                if (rr >= N_NODES) continue;
                float v0 = acc[m][n][h * 2], v1 = acc[m][n][h * 2 + 1];
                if (c < OUTD_F) {
                    *(__half2*)(g_uh + (size_t)rr * OUTD_F + c) = __floats2half2_rn(v0, v1);
                } else {
                    g_v[(size_t)rr * OUTD_F + c - OUTD_F]     = v0 + bias[c - OUTD_F];
                    g_v[(size_t)rr * OUTD_F + c - OUTD_F + 1] = v1 + bias[c - OUTD_F + 1];
                }
            }
        }
    }
}

// ---------------- fused: gather-mean(U bf16) + V, L2-norm, ReLU, bf16 ------
// one warp per node; lane handles cols [4*lane, 4*lane+3]; pipelined indices.
__global__ void k_aggnorm() {
    int warp = (blockIdx.x * blockDim.x + threadIdx.x) >> 5;
    int lane = threadIdx.x & 31;
    if (warp >= N_NODES) return;
    int n = warp;
    const uint2* __restrict__ U2 = (const uint2*)g_Ub;   // row = 32 uint2 (128 bf16)
    const int* __restrict__ csc = g_csc;
    int j = g_off[n], je = g_off[n + 1];
    float ax = 0.f, ay = 0.f, az = 0.f, aw = 0.f;

    int s0 = 0, s1 = 0, s2 = 0, s3 = 0;
    if (j + 3 < je) {
        s0 = __ldg(&csc[j]);     s1 = __ldg(&csc[j + 1]);
        s2 = __ldg(&csc[j + 2]); s3 = __ldg(&csc[j + 3]);
    }
    while (j + 3 < je) {
        uint2 w0 = __ldg(&U2[(size_t)s0 * 32 + lane]);
        uint2 w1 = __ldg(&U2[(size_t)s1 * 32 + lane]);
        uint2 w2 = __ldg(&U2[(size_t)s2 * 32 + lane]);
        uint2 w3 = __ldg(&U2[(size_t)s3 * 32 + lane]);
        int jn = j + 4;
        if (jn + 3 < je) {
            s0 = __ldg(&csc[jn]);     s1 = __ldg(&csc[jn + 1]);
            s2 = __ldg(&csc[jn + 2]); s3 = __ldg(&csc[jn + 3]);
        }
        ax += bf_lo(w0.x) + bf_lo(w1.x) + bf_lo(w2.x) + bf_lo(w3.x);
        ay += bf_hi(w0.x) + bf_hi(w1.x) + bf_hi(w2.x) + bf_hi(w3.x);
        az += bf_lo(w0.y) + bf_lo(w1.y) + bf_lo(w2.y) + bf_lo(w3.y);
        aw += bf_hi(w0.y) + bf_hi(w1.y) + bf_hi(w2.y) + bf_hi(w3.y);
        j = jn;
    }
    for (; j < je; j++) {
        uint2 w0 = __ldg(&U2[(size_t)__ldg(&csc[j]) * 32 + lane]);
        ax += bf_lo(w0.x); ay += bf_hi(w0.x);
        az += bf_lo(w0.y); aw += bf_hi(w0.y);
    }
    float inv_d = g_invdeg[n];
    float4 vv = ((const float4*)g_V)[(size_t)n * 32 + lane];
    ax = ax * inv_d + vv.x;
    ay = ay * inv_d + vv.y;
    az = az * inv_d + vv.z;
    aw = aw * inv_d + vv.w;

    float ss = ax * ax + ay * ay + az * az + aw * aw;
#pragma unroll
    for (int s = 16; s; s >>= 1) ss += __shfl_xor_sync(0xFFFFFFFFu, ss, s);
    float sc = 1.0f / fmaxf(sqrtf(ss), 1e-12f);
    ax = fmaxf(ax * sc, 0.f);
    ay = fmaxf(ay * sc, 0.f);
    az = fmaxf(az * sc, 0.f);
    aw = fmaxf(aw * sc, 0.f);

    // single bf16 copy of h (A operand for next GEMM)
    size_t widx = ((size_t)n * DIMF + lane * 4) >> 1;   // unsigned index
    unsigned* xo = (unsigned*)g_xhi;
    xo[widx]     = bf_pack(ax, ay);
    xo[widx + 1] = bf_pack(az, aw);
}

// ---------------- layer-2: gather u(fp16), add v, softmax ------------------
__global__ void k_agg_softmax(float* __restrict__ out) {
    int warp = (blockIdx.x * blockDim.x + threadIdx.x) >> 5;
    int lane = threadIdx.x & 31;
    if (warp >= N_NODES) return;
    int n = warp;
    bool act = lane < 20;                        // 2 cols per active lane
    const __half2* __restrict__ u2 = (const __half2*)g_uh;   // row = 20 half2
    const int* __restrict__ csc = g_csc;
    int j = g_off[n], je = g_off[n + 1];
    float acc0 = 0.f, acc1 = 0.f;

    int s0 = 0, s1 = 0, s2 = 0, s3 = 0;
    if (j + 3 < je) {
        s0 = __ldg(&csc[j]);     s1 = __ldg(&csc[j + 1]);
        s2 = __ldg(&csc[j + 2]); s3 = __ldg(&csc[j + 3]);
    }
    while (j + 3 < je) {
        float2 f0, f1, f2, f3;
        if (act) {
            f0 = __half22float2(__ldg(&u2[(size_t)s0 * 20 + lane]));
            f1 = __half22float2(__ldg(&u2[(size_t)s1 * 20 + lane]));
            f2 = __half22float2(__ldg(&u2[(size_t)s2 * 20 + lane]));
            f3 = __half22float2(__ldg(&u2[(size_t)s3 * 20 + lane]));
        }
        int jn = j + 4;
        if (jn + 3 < je) {
            s0 = __ldg(&csc[jn]);     s1 = __ldg(&csc[jn + 1]);
            s2 = __ldg(&csc[jn + 2]); s3 = __ldg(&csc[jn + 3]);
        }
        if (act) {
            acc0 += f0.x + f1.x + f2.x + f3.x;
            acc1 += f0.y + f1.y + f2.y + f3.y;
        }
        j = jn;
    }
    for (; j < je; j++) {
        int s = __ldg(&csc[j]);
        if (act) {
            float2 f0 = __half22float2(__ldg(&u2[(size_t)s * 20 + lane]));
            acc0 += f0.x; acc1 += f0.y;
        }
    }
    float inv_d = g_invdeg[n];
    float a0 = -1e30f, a1 = -1e30f;
    if (act) {
        a0 = acc0 * inv_d + g_v[(size_t)n * OUTD_F + lane * 2];
        a1 = acc1 * inv_d + g_v[(size_t)n * OUTD_F + lane * 2 + 1];
    }
    float m = fmaxf(a0, a1);
#pragma unroll
    for (int s = 16; s; s >>= 1) m = fmaxf(m, __shfl_xor_sync(0xFFFFFFFFu, m, s));
    float e0 = act ? __expf(a0 - m) : 0.f;
    float e1 = act ? __expf(a1 - m) : 0.f;
    float sum = e0 + e1;
#pragma unroll
    for (int s = 16; s; s >>= 1) sum += __shfl_xor_sync(0xFFFFFFFFu, sum, s);
    float inv = 1.0f / sum;
    if (act) {
        float* row = out + (size_t)n * OUTD_F + lane * 2;
        row[0] = e0 * inv;
        row[1] = e1 * inv;
    }
}

// ---------------- launch ----------------------------------------------------
extern "C" void kernel_launch(void* const* d_in, const int* in_sizes, int n_in,
                              void* d_out, int out_size) {
    const float* x   = (const float*)d_in[0];
    const int*   e32 = (const int*)d_in[1];
    const float* Wl0 = (const float*)d_in[2];
    const float* Wr0 = (const float*)d_in[3];
    const float* b0  = (const float*)d_in[4];
    const float* Wl1 = (const float*)d_in[5];
    const float* Wr1 = (const float*)d_in[6];
    const float* b1  = (const float*)d_in[7];
    const float* Wl2 = (const float*)d_in[8];
    const float* Wr2 = (const float*)d_in[9];
    const float* b2  = (const float*)d_in[10];
    float* out = (float*)d_out;

    const int TB = 256;
    int nblk_nodes = (N_NODES + TB - 1) / TB;
    int nblk_edges = (N_EDGES + TB - 1) / TB;
    int nblk_gemm  = (N_NODES + 127) / 128;    // 782
    int nblk_wnode = (N_NODES + 7) / 8;        // warp-per-node

    // ---- dtype detect + build CSC ----
    k_detect<<<1, TB>>>(e32);
    k_zero_deg<<<nblk_nodes, TB>>>();
    k_hist<<<nblk_edges, TB>>>(e32);
    k_scan1<<<NB_SCAN, SCAN_B>>>();
    k_scan2<<<1, 128>>>();
    k_scan3<<<nblk_nodes, TB>>>();
    k_fill_csc<<<nblk_edges, TB>>>(e32);

    // ---- layer 0 (fp32 x read directly by GEMM) ----
    k_split_w<<<(DIMF * DIMF + TB - 1) / TB, TB>>>(Wl0, Wr0, DIMF * DIMF);
    k_gemm_l01<true><<<dim3(nblk_gemm, 2), TB>>>(x, b0);
    k_aggnorm<<<nblk_wnode, TB>>>();

    // ---- layer 1 ----
    k_split_w<<<(DIMF * DIMF + TB - 1) / TB, TB>>>(Wl1, Wr1, DIMF * DIMF);
    k_gemm_l01<false><<<dim3(nblk_gemm, 2), TB>>>(nullptr, b1);
    k_aggnorm<<<nblk_wnode, TB>>>();

    // ---- layer 2 (project-first, fp16 u gather + fused softmax) ----
    k_split_w2<<<(OUTD_F * DIMF + TB - 1) / TB, TB>>>(Wl2, Wr2);
    k_gemm2<<<nblk_gemm, TB>>>(b2);
    k_agg_softmax<<<nblk_wnode, TB>>>(out);
}

// round 14
// speedup vs baseline: 1.9797x; 1.0440x over previous
#include <cuda_runtime.h>
#include <cuda_bf16.h>
#include <cuda_fp16.h>
#include <math.h>

#define N_NODES 100000
#define N_EDGES 1600000
#define DIMF    128
#define OUTD_F  40
#define SCAN_B  1024
#define NB_SCAN 98   // ceil(100000/1024)

// ---------------- scratch (device globals; no allocation allowed) ----------
__device__ int   g_is64;
__device__ int   g_deg[N_NODES];
__device__ float g_invdeg[N_NODES];
__device__ int   g_off[N_NODES + 1];
__device__ int   g_cursor[N_NODES];
__device__ int   g_bsums[NB_SCAN];
__device__ int   g_csc[N_EDGES];
__device__ __align__(16) unsigned short g_Ub[(size_t)N_NODES * DIMF]; // X@Wl^T, bf16 bits
__device__ __align__(16) float  g_V [(size_t)N_NODES * DIMF];          // X@Wr^T + b
__device__ __align__(16) __half g_uh[(size_t)N_NODES * OUTD_F];        // layer2: h1@Wl2^T
__device__ __align__(16) float  g_v [(size_t)N_NODES * OUTD_F];        // layer2: h1@Wr2^T + b2
// activations: single bf16 copy (A operand); weights: bf16 hi/lo split, per layer
__device__ __align__(16) __nv_bfloat16 g_xhi[(size_t)N_NODES * DIMF];
__device__ __align__(16) __nv_bfloat16 g_W0lhi[DIMF*DIMF], g_W0llo[DIMF*DIMF];
__device__ __align__(16) __nv_bfloat16 g_W0rhi[DIMF*DIMF], g_W0rlo[DIMF*DIMF];
__device__ __align__(16) __nv_bfloat16 g_W1lhi[DIMF*DIMF], g_W1llo[DIMF*DIMF];
__device__ __align__(16) __nv_bfloat16 g_W1rhi[DIMF*DIMF], g_W1rlo[DIMF*DIMF];
__device__ __align__(16) __nv_bfloat16 g_W2hi[2*OUTD_F*DIMF], g_W2lo[2*OUTD_F*DIMF];

__device__ __forceinline__ int edge_at(const int* __restrict__ e32, int i) {
    return g_is64 ? e32[2 * i] : e32[i];
}
__device__ __forceinline__ void split2(float v, __nv_bfloat16& hi, __nv_bfloat16& lo) {
    hi = __float2bfloat16(v);
    lo = __float2bfloat16(v - __bfloat162float(hi));
}
__device__ __forceinline__ float bf_lo(unsigned w) { return __uint_as_float(w << 16); }
__device__ __forceinline__ float bf_hi(unsigned w) { return __uint_as_float(w & 0xFFFF0000u); }
__device__ __forceinline__ unsigned bf_pack(float a, float b) {
    return (unsigned)__bfloat16_as_ushort(__float2bfloat16(a)) |
           ((unsigned)__bfloat16_as_ushort(__float2bfloat16(b)) << 16);
}

// ---------------- dtype detection ------------------------------------------
__global__ void k_detect(const int* __restrict__ e32) {
    __shared__ int nonzero;
    if (threadIdx.x == 0) nonzero = 0;
    __syncthreads();
    for (int i = threadIdx.x; i < 1024; i += blockDim.x)
        if (e32[2 * i + 1] != 0) nonzero = 1;
    __syncthreads();
    if (threadIdx.x == 0) g_is64 = (nonzero == 0);
}

// ---------------- graph preprocessing --------------------------------------
__global__ void k_zero_deg() {
    int i = blockIdx.x * blockDim.x + threadIdx.x;
    if (i < N_NODES) g_deg[i] = 0;
}

__global__ void k_hist(const int* __restrict__ e32) {
    int e = blockIdx.x * blockDim.x + threadIdx.x;
    if (e < N_EDGES) {
        int d = edge_at(e32, N_EDGES + e);
        if ((unsigned)d < N_NODES) atomicAdd(&g_deg[d], 1);
    }
}

__global__ void k_scan1() {
    __shared__ int sh[SCAN_B];
    int t = threadIdx.x;
    int i = blockIdx.x * SCAN_B + t;
    int v = (i < N_NODES) ? g_deg[i] : 0;
    sh[t] = v;
    __syncthreads();
    for (int s = 1; s < SCAN_B; s <<= 1) {
        int prev = (t >= s) ? sh[t - s] : 0;
        __syncthreads();
        sh[t] += prev;
        __syncthreads();
    }
    if (i < N_NODES) g_off[i] = sh[t] - v;
    if (t == SCAN_B - 1) g_bsums[blockIdx.x] = sh[t];
}

__global__ void k_scan2() {
    __shared__ int sh[128];
    int t = threadIdx.x;
    int v = (t < NB_SCAN) ? g_bsums[t] : 0;
    sh[t] = v;
    __syncthreads();
#pragma unroll
    for (int s = 1; s < 128; s <<= 1) {
        int prev = (t >= s) ? sh[t - s] : 0;
        __syncthreads();
        sh[t] += prev;
        __syncthreads();
    }
    if (t < NB_SCAN) g_bsums[t] = sh[t] - v;   // exclusive
}

__global__ void k_scan3() {
    int i = blockIdx.x * blockDim.x + threadIdx.x;
    if (i < N_NODES) {
        int o = g_off[i] + g_bsums[i >> 10];
        g_off[i] = o;
        g_cursor[i] = o;
        int d = g_deg[i];
        g_invdeg[i] = 1.0f / (float)(d > 1 ? d : 1);
    }
    if (i == 0) g_off[N_NODES] = N_EDGES;
}

__global__ void k_fill_csc(const int* __restrict__ e32) {
    int e = blockIdx.x * blockDim.x + threadIdx.x;
    if (e < N_EDGES) {
        int s = edge_at(e32, e);
        int d = edge_at(e32, N_EDGES + e);
        if ((unsigned)s < N_NODES && (unsigned)d < N_NODES) {
            int p = atomicAdd(&g_cursor[d], 1);
            g_csc[p] = s;
        }
    }
}

// ---------------- weight splitting (per layer, separate buffers) -----------
template <int L>
__global__ void k_split_w(const float* __restrict__ Wl, const float* __restrict__ Wr) {
    int i = blockIdx.x * blockDim.x + threadIdx.x;
    __nv_bfloat16 hi, lo;
    if (L < 2) {
        if (i < DIMF * DIMF) {
            split2(Wl[i], hi, lo);
            if (L == 0) { g_W0lhi[i] = hi; g_W0llo[i] = lo; }
            else        { g_W1lhi[i] = hi; g_W1llo[i] = lo; }
            split2(Wr[i], hi, lo);
            if (L == 0) { g_W0rhi[i] = hi; g_W0rlo[i] = lo; }
            else        { g_W1rhi[i] = hi; g_W1rlo[i] = lo; }
        }
    } else {
        int n = OUTD_F * DIMF;
        if (i < n) {
            split2(Wl[i], hi, lo); g_W2hi[i] = hi;     g_W2lo[i] = lo;
            split2(Wr[i], hi, lo); g_W2hi[n + i] = hi; g_W2lo[n + i] = lo;
        }
    }
}

// ---------------- tensor-core GEMM ------------------------------------------
__device__ __forceinline__ void mma_bf16(float* d, const unsigned* a, unsigned b0, unsigned b1) {
    asm volatile(
        "mma.sync.aligned.m16n8k16.row.col.f32.bf16.bf16.f32 "
        "{%0,%1,%2,%3}, {%4,%5,%6,%7}, {%8,%9}, {%0,%1,%2,%3};\n"
        : "+f"(d[0]), "+f"(d[1]), "+f"(d[2]), "+f"(d[3])
        : "r"(a[0]), "r"(a[1]), "r"(a[2]), "r"(a[3]), "r"(b0), "r"(b1));
}

// layers 0/1: blockIdx.y==0 -> U(bf16) = X@Wl^T ; ==1 -> V(f32) = X@Wr^T + b
// bf16x2: D = A_bf16 * (W_hi + W_lo). FP32A: layer 0 reads fp32 x directly.
template <bool FP32A>
__global__ void __launch_bounds__(256) k_gemm_l01(const float* __restrict__ xin,
                                                  const float* __restrict__ bias, int layer) {
    constexpr int OUTD = 128;
    constexpr int MT = 2, NT = 8, STR = 20;

    __shared__ __align__(16) unsigned sAh[128 * STR];
    __shared__ __align__(16) unsigned sWh[OUTD * STR], sWl[OUTD * STR];

    int side = blockIdx.y;
    const unsigned* Ah = (const unsigned*)g_xhi;
    const unsigned* Wh;
    const unsigned* Wo;
    if (layer == 0) {
        Wh = (const unsigned*)(side ? g_W0rhi : g_W0lhi);
        Wo = (const unsigned*)(side ? g_W0rlo : g_W0llo);
    } else {
        Wh = (const unsigned*)(side ? g_W1rhi : g_W1lhi);
        Wo = (const unsigned*)(side ? g_W1rlo : g_W1llo);
    }

    int tid  = threadIdx.x;
    int wid  = tid >> 5, lane = tid & 31;
    int mw   = wid & 3, nw = wid >> 2;
    int row0 = blockIdx.x * 128;
    int lg   = lane >> 2, lt = lane & 3;

    float acc[MT][NT][4];
#pragma unroll
    for (int m = 0; m < MT; m++)
#pragma unroll
        for (int n = 0; n < NT; n++)
#pragma unroll
            for (int q = 0; q < 4; q++) acc[m][n][q] = 0.f;

#pragma unroll 1
    for (int kt = 0; kt < 4; kt++) {
        int kw = kt * 16;

        if (FP32A) {
#pragma unroll
            for (int i = tid; i < 1024; i += 256) {
                int r = i >> 3, q = (i & 7) * 4;
                float4 v = make_float4(0.f, 0.f, 0.f, 0.f);
                if (row0 + r < N_NODES)
                    v = *(const float4*)(xin + (size_t)(row0 + r) * DIMF + kt * 32 + q);
                int wq = q >> 1;
                sAh[r * STR + wq]     = bf_pack(v.x, v.y);
                sAh[r * STR + wq + 1] = bf_pack(v.z, v.w);
            }
        } else {
#pragma unroll
            for (int i = tid; i < 128 * 4; i += 256) {
                int r = i >> 2, q = (i & 3) * 4;
                uint4 vh = make_uint4(0, 0, 0, 0);
                if (row0 + r < N_NODES)
                    vh = *(const uint4*)(Ah + (size_t)(row0 + r) * 64 + kw + q);
                *(uint4*)(sAh + r * STR + q) = vh;
            }
        }
        for (int i = tid; i < OUTD * 4; i += 256) {
            int r = i >> 2, q = (i & 3) * 4;
            *(uint4*)(sWh + r * STR + q) = *(const uint4*)(Wh + (size_t)r * 64 + kw + q);
            *(uint4*)(sWl + r * STR + q) = *(const uint4*)(Wo + (size_t)r * 64 + kw + q);
        }
        __syncthreads();

#pragma unroll
        for (int ks = 0; ks < 2; ks++) {
            int wb = ks * 8;
            unsigned ah[MT][4];
#pragma unroll
            for (int m = 0; m < MT; m++) {
                int rr = (mw * MT + m) * 16 + lg;
                ah[m][0] = sAh[rr * STR + wb + lt];
                ah[m][1] = sAh[(rr + 8) * STR + wb + lt];
                ah[m][2] = sAh[rr * STR + wb + 4 + lt];
                ah[m][3] = sAh[(rr + 8) * STR + wb + 4 + lt];
            }
#pragma unroll
            for (int n = 0; n < NT; n++) {
                int nr = nw * NT * 8 + n * 8 + lg;
                unsigned bh0 = sWh[nr * STR + wb + lt];
                unsigned bh1 = sWh[nr * STR + wb + 4 + lt];
                unsigned bl0 = sWl[nr * STR + wb + lt];
                unsigned bl1 = sWl[nr * STR + wb + 4 + lt];
#pragma unroll
                for (int m = 0; m < MT; m++) {
                    mma_bf16(acc[m][n], ah[m], bh0, bh1);
                    mma_bf16(acc[m][n], ah[m], bl0, bl1);
                }
            }
        }
        __syncthreads();
    }

#pragma unroll
    for (int m = 0; m < MT; m++) {
        int r = row0 + (mw * MT + m) * 16 + lg;
#pragma unroll
        for (int n = 0; n < NT; n++) {
            int c = nw * NT * 8 + n * 8 + lt * 2;
#pragma unroll
            for (int h = 0; h < 2; h++) {
                int rr = r + h * 8;
                if (rr >= N_NODES) continue;
                float v0 = acc[m][n][h * 2], v1 = acc[m][n][h * 2 + 1];
                if (side) {
                    g_V[(size_t)rr * OUTD + c]     = v0 + bias[c];
                    g_V[(size_t)rr * OUTD + c + 1] = v1 + bias[c + 1];
                } else {
                    *(unsigned*)(g_Ub + (size_t)rr * OUTD + c) = bf_pack(v0, v1);
                }
            }
        }
    }
}

// layer 2: [u|v] = h1 @ [Wl2;Wr2]^T; u -> fp16, v -> f32 + bias. bf16x2.
__global__ void __launch_bounds__(256) k_gemm2(const float* __restrict__ bias) {
    constexpr int OUTD = 80;
    constexpr int MT = 2, NT = 5, STR = 20;

    __shared__ __align__(16) unsigned sAh[128 * STR];
    __shared__ __align__(16) unsigned sWh[OUTD * STR], sWl[OUTD * STR];

    int tid  = threadIdx.x;
    int wid  = tid >> 5, lane = tid & 31;
    int mw   = wid & 3, nw = wid >> 2;
    int row0 = blockIdx.x * 128;
    int lg   = lane >> 2, lt = lane & 3;

    float acc[MT][NT][4];
#pragma unroll
    for (int m = 0; m < MT; m++)
#pragma unroll
        for (int n = 0; n < NT; n++)
#pragma unroll
            for (int q = 0; q < 4; q++) acc[m][n][q] = 0.f;

    const unsigned* Ah = (const unsigned*)g_xhi;
    const unsigned* Wh = (const unsigned*)g_W2hi;
    const unsigned* Wo = (const unsigned*)g_W2lo;

#pragma unroll 1
    for (int kt = 0; kt < 4; kt++) {
        int kw = kt * 16;

#pragma unroll
        for (int i = tid; i < 128 * 4; i += 256) {
            int r = i >> 2, q = (i & 3) * 4;
            uint4 vh = make_uint4(0, 0, 0, 0);
            if (row0 + r < N_NODES)
                vh = *(const uint4*)(Ah + (size_t)(row0 + r) * 64 + kw + q);
            *(uint4*)(sAh + r * STR + q) = vh;
        }
        for (int i = tid; i < OUTD * 4; i += 256) {
            int r = i >> 2, q = (i & 3) * 4;
            *(uint4*)(sWh + r * STR + q) = *(const uint4*)(Wh + (size_t)r * 64 + kw + q);
            *(uint4*)(sWl + r * STR + q) = *(const uint4*)(Wo + (size_t)r * 64 + kw + q);
        }
        __syncthreads();

#pragma unroll
        for (int ks = 0; ks < 2; ks++) {
            int wb = ks * 8;
            unsigned ah[MT][4];
#pragma unroll
            for (int m = 0; m < MT; m++) {
                int rr = (mw * MT + m) * 16 + lg;
                ah[m][0] = sAh[rr * STR + wb + lt];
                ah[m][1] = sAh[(rr + 8) * STR + wb + lt];
                ah[m][2] = sAh[rr * STR + wb + 4 + lt];
                ah[m][3] = sAh[(rr + 8) * STR + wb + 4 + lt];
            }
#pragma unroll
            for (int n = 0; n < NT; n++) {
                int nr = nw * NT * 8 + n * 8 + lg;
                unsigned bh0 = sWh[nr * STR + wb + lt];
                unsigned bh1 = sWh[nr * STR + wb + 4 + lt];
                unsigned bl0 = sWl[nr * STR + wb + lt];
                unsigned bl1 = sWl[nr * STR + wb + 4 + lt];
#pragma unroll
                for (int m = 0; m < MT; m++) {
                    mma_bf16(acc[m][n], ah[m], bh0, bh1);
                    mma_bf16(acc[m][n], ah[m], bl0, bl1);
                }
            }
        }
        __syncthreads();
    }

#pragma unroll
    for (int m = 0; m < MT; m++) {
        int r = row0 + (mw * MT + m) * 16 + lg;
#pragma unroll
        for (int n = 0; n < NT; n++) {
            int c = nw * NT * 8 + n * 8 + lt * 2;
#pragma unroll
            for (int h = 0; h < 2; h++) {
                int rr = r + h * 8;
                if (rr >= N_NODES) continue;
                float v0 = acc[m][n][h * 2], v1 = acc[m][n][h * 2 + 1];
                if (c < OUTD_F) {
                    *(__half2*)(g_uh + (size_t)rr * OUTD_F + c) = __floats2half2_rn(v0, v1);
                } else {
                    g_v[(size_t)rr * OUTD_F + c - OUTD_F]     = v0 + bias[c - OUTD_F];
                    g_v[(size_t)rr * OUTD_F + c - OUTD_F + 1] = v1 + bias[c - OUTD_F + 1];
                }
            }
        }
    }
}

// ---------------- fused: gather-mean(U bf16) + V, L2-norm, ReLU, bf16 ------
__global__ void k_aggnorm() {
    int warp = (blockIdx.x * blockDim.x + threadIdx.x) >> 5;
    int lane = threadIdx.x & 31;
    if (warp >= N_NODES) return;
    int n = warp;
    const uint2* __restrict__ U2 = (const uint2*)g_Ub;
    const int* __restrict__ csc = g_csc;
    int j = g_off[n], je = g_off[n + 1];
    float ax = 0.f, ay = 0.f, az = 0.f, aw = 0.f;

    int s0 = 0, s1 = 0, s2 = 0, s3 = 0;
    if (j + 3 < je) {
        s0 = __ldg(&csc[j]);     s1 = __ldg(&csc[j + 1]);
        s2 = __ldg(&csc[j + 2]); s3 = __ldg(&csc[j + 3]);
    }
    while (j + 3 < je) {
        uint2 w0 = __ldg(&U2[(size_t)s0 * 32 + lane]);
        uint2 w1 = __ldg(&U2[(size_t)s1 * 32 + lane]);
        uint2 w2 = __ldg(&U2[(size_t)s2 * 32 + lane]);
        uint2 w3 = __ldg(&U2[(size_t)s3 * 32 + lane]);
        int jn = j + 4;
        if (jn + 3 < je) {
            s0 = __ldg(&csc[jn]);     s1 = __ldg(&csc[jn + 1]);
            s2 = __ldg(&csc[jn + 2]); s3 = __ldg(&csc[jn + 3]);
        }
        ax += bf_lo(w0.x) + bf_lo(w1.x) + bf_lo(w2.x) + bf_lo(w3.x);
        ay += bf_hi(w0.x) + bf_hi(w1.x) + bf_hi(w2.x) + bf_hi(w3.x);
        az += bf_lo(w0.y) + bf_lo(w1.y) + bf_lo(w2.y) + bf_lo(w3.y);
        aw += bf_hi(w0.y) + bf_hi(w1.y) + bf_hi(w2.y) + bf_hi(w3.y);
        j = jn;
    }
    for (; j < je; j++) {
        uint2 w0 = __ldg(&U2[(size_t)__ldg(&csc[j]) * 32 + lane]);
        ax += bf_lo(w0.x); ay += bf_hi(w0.x);
        az += bf_lo(w0.y); aw += bf_hi(w0.y);
    }
    float inv_d = g_invdeg[n];
    float4 vv = ((const float4*)g_V)[(size_t)n * 32 + lane];
    ax = ax * inv_d + vv.x;
    ay = ay * inv_d + vv.y;
    az = az * inv_d + vv.z;
    aw = aw * inv_d + vv.w;

    float ss = ax * ax + ay * ay + az * az + aw * aw;
#pragma unroll
    for (int s = 16; s; s >>= 1) ss += __shfl_xor_sync(0xFFFFFFFFu, ss, s);
    float sc = 1.0f / fmaxf(sqrtf(ss), 1e-12f);
    ax = fmaxf(ax * sc, 0.f);
    ay = fmaxf(ay * sc, 0.f);
    az = fmaxf(az * sc, 0.f);
    aw = fmaxf(aw * sc, 0.f);

    size_t widx = ((size_t)n * DIMF + lane * 4) >> 1;
    unsigned* xo = (unsigned*)g_xhi;
    xo[widx]     = bf_pack(ax, ay);
    xo[widx + 1] = bf_pack(az, aw);
}

// ---------------- layer-2: gather u(fp16), add v, softmax ------------------
__global__ void k_agg_softmax(float* __restrict__ out) {
    int warp = (blockIdx.x * blockDim.x + threadIdx.x) >> 5;
    int lane = threadIdx.x & 31;
    if (warp >= N_NODES) return;
    int n = warp;
    bool act = lane < 20;
    const __half2* __restrict__ u2 = (const __half2*)g_uh;
    const int* __restrict__ csc = g_csc;
    int j = g_off[n], je = g_off[n + 1];
    float acc0 = 0.f, acc1 = 0.f;

    int s0 = 0, s1 = 0, s2 = 0, s3 = 0;
    if (j + 3 < je) {
        s0 = __ldg(&csc[j]);     s1 = __ldg(&csc[j + 1]);
        s2 = __ldg(&csc[j + 2]); s3 = __ldg(&csc[j + 3]);
    }
    while (j + 3 < je) {
        float2 f0, f1, f2, f3;
        if (act) {
            f0 = __half22float2(__ldg(&u2[(size_t)s0 * 20 + lane]));
            f1 = __half22float2(__ldg(&u2[(size_t)s1 * 20 + lane]));
            f2 = __half22float2(__ldg(&u2[(size_t)s2 * 20 + lane]));
            f3 = __half22float2(__ldg(&u2[(size_t)s3 * 20 + lane]));
        }
        int jn = j + 4;
        if (jn + 3 < je) {
            s0 = __ldg(&csc[jn]);     s1 = __ldg(&csc[jn + 1]);
            s2 = __ldg(&csc[jn + 2]); s3 = __ldg(&csc[jn + 3]);
        }
        if (act) {
            acc0 += f0.x + f1.x + f2.x + f3.x;
            acc1 += f0.y + f1.y + f2.y + f3.y;
        }
        j = jn;
    }
    for (; j < je; j++) {
        int s = __ldg(&csc[j]);
        if (act) {
            float2 f0 = __half22float2(__ldg(&u2[(size_t)s * 20 + lane]));
            acc0 += f0.x; acc1 += f0.y;
        }
    }
    float inv_d = g_invdeg[n];
    float a0 = -1e30f, a1 = -1e30f;
    if (act) {
        a0 = acc0 * inv_d + g_v[(size_t)n * OUTD_F + lane * 2];
        a1 = acc1 * inv_d + g_v[(size_t)n * OUTD_F + lane * 2 + 1];
    }
    float m = fmaxf(a0, a1);
#pragma unroll
    for (int s = 16; s; s >>= 1) m = fmaxf(m, __shfl_xor_sync(0xFFFFFFFFu, m, s));
    float e0 = act ? __expf(a0 - m) : 0.f;
    float e1 = act ? __expf(a1 - m) : 0.f;
    float sum = e0 + e1;
#pragma unroll
    for (int s = 16; s; s >>= 1) sum += __shfl_xor_sync(0xFFFFFFFFu, sum, s);
    float inv = 1.0f / sum;
    if (act) {
        float* row = out + (size_t)n * OUTD_F + lane * 2;
        row[0] = e0 * inv;
        row[1] = e1 * inv;
    }
}

// ---------------- launch ----------------------------------------------------
extern "C" void kernel_launch(void* const* d_in, const int* in_sizes, int n_in,
                              void* d_out, int out_size) {
    const float* x   = (const float*)d_in[0];
    const int*   e32 = (const int*)d_in[1];
    const float* Wl0 = (const float*)d_in[2];
    const float* Wr0 = (const float*)d_in[3];
    const float* b0  = (const float*)d_in[4];
    const float* Wl1 = (const float*)d_in[5];
    const float* Wr1 = (const float*)d_in[6];
    const float* b1  = (const float*)d_in[7];
    const float* Wl2 = (const float*)d_in[8];
    const float* Wr2 = (const float*)d_in[9];
    const float* b2  = (const float*)d_in[10];
    float* out = (float*)d_out;

    const int TB = 256;
    int nblk_nodes = (N_NODES + TB - 1) / TB;
    int nblk_edges = (N_EDGES + TB - 1) / TB;
    int nblk_gemm  = (N_NODES + 127) / 128;    // 782
    int nblk_wnode = (N_NODES + 7) / 8;        // warp-per-node
    int nblk_w01   = (DIMF * DIMF + TB - 1) / TB;
    int nblk_w2    = (OUTD_F * DIMF + TB - 1) / TB;

    // fork a side stream for the CSC build (independent of layer-0 GEMM).
    // streams/events are intentionally leaked: destroying them mid-capture
    // is illegal, and kernel_launch only runs twice (correctness + capture).
    cudaStream_t side;
    cudaEvent_t evFork, evCsc;
    cudaStreamCreateWithFlags(&side, cudaStreamNonBlocking);
    cudaEventCreateWithFlags(&evFork, cudaEventDisableTiming);
    cudaEventCreateWithFlags(&evCsc, cudaEventDisableTiming);

    cudaEventRecord(evFork, 0);
    cudaStreamWaitEvent(side, evFork, 0);

    // ---- side stream: dtype detect + CSC build ----
    k_detect<<<1, TB, 0, side>>>(e32);
    k_zero_deg<<<nblk_nodes, TB, 0, side>>>();
    k_hist<<<nblk_edges, TB, 0, side>>>(e32);
    k_scan1<<<NB_SCAN, SCAN_B, 0, side>>>();
    k_scan2<<<1, 128, 0, side>>>();
    k_scan3<<<nblk_nodes, TB, 0, side>>>();
    k_fill_csc<<<nblk_edges, TB, 0, side>>>(e32);
    cudaEventRecord(evCsc, side);

    // ---- main stream: all weight splits + layer-0 GEMM (independent) ----
    k_split_w<0><<<nblk_w01, TB>>>(Wl0, Wr0);
    k_split_w<1><<<nblk_w01, TB>>>(Wl1, Wr1);
    k_split_w<2><<<nblk_w2, TB>>>(Wl2, Wr2);
    k_gemm_l01<true><<<dim3(nblk_gemm, 2), TB>>>(x, b0, 0);

    // ---- join: aggnorm needs CSC + U/V ----
    cudaStreamWaitEvent(0, evCsc, 0);
    k_aggnorm<<<nblk_wnode, TB>>>();

    // ---- layer 1 ----
    k_gemm_l01<false><<<dim3(nblk_gemm, 2), TB>>>(nullptr, b1, 1);
    k_aggnorm<<<nblk_wnode, TB>>>();

    // ---- layer 2 ----
    k_gemm2<<<nblk_gemm, TB>>>(b2);
    k_agg_softmax<<<nblk_wnode, TB>>>(out);
}

// round 15
// speedup vs baseline: 2.1574x; 1.0898x over previous
#include <cuda_runtime.h>
#include <cuda_bf16.h>
#include <cuda_fp16.h>
#include <math.h>

#define N_NODES 100000
#define N_EDGES 1600000
#define DIMF    128
#define OUTD_F  40
#define SCAN_B  1024
#define NB_SCAN 98   // ceil(100000/1024)

// ---------------- scratch (device globals; no allocation allowed) ----------
__device__ int   g_is64;
__device__ int   g_deg[N_NODES];
__device__ float g_invdeg[N_NODES];
__device__ int   g_off[N_NODES + 1];
__device__ int   g_cursor[N_NODES];
__device__ int   g_bsums[NB_SCAN];
__device__ int   g_csc[N_EDGES];
__device__ __align__(16) unsigned short g_Ub[(size_t)N_NODES * DIMF]; // X@Wl^T, bf16 bits
__device__ __align__(16) float  g_V [(size_t)N_NODES * DIMF];          // X@Wr^T + b
__device__ __align__(16) __half g_uh[(size_t)N_NODES * OUTD_F];        // layer2: h1@Wl2^T
__device__ __align__(16) float  g_v [(size_t)N_NODES * OUTD_F];        // layer2: h1@Wr2^T + b2
// activations + weights: single bf16 copies
__device__ __align__(16) __nv_bfloat16 g_xhi[(size_t)N_NODES * DIMF];
__device__ __align__(16) __nv_bfloat16 g_W0l[DIMF*DIMF], g_W0r[DIMF*DIMF];
__device__ __align__(16) __nv_bfloat16 g_W1l[DIMF*DIMF], g_W1r[DIMF*DIMF];
__device__ __align__(16) __nv_bfloat16 g_W2 [2*OUTD_F*DIMF];

__device__ __forceinline__ int edge_at(const int* __restrict__ e32, int i) {
    return g_is64 ? e32[2 * i] : e32[i];
}
__device__ __forceinline__ float bf_lo(unsigned w) { return __uint_as_float(w << 16); }
__device__ __forceinline__ float bf_hi(unsigned w) { return __uint_as_float(w & 0xFFFF0000u); }
__device__ __forceinline__ unsigned bf_pack(float a, float b) {
    return (unsigned)__bfloat16_as_ushort(__float2bfloat16(a)) |
           ((unsigned)__bfloat16_as_ushort(__float2bfloat16(b)) << 16);
}

// ---------------- dtype detection ------------------------------------------
__global__ void k_detect(const int* __restrict__ e32) {
    __shared__ int nonzero;
    if (threadIdx.x == 0) nonzero = 0;
    __syncthreads();
    for (int i = threadIdx.x; i < 1024; i += blockDim.x)
        if (e32[2 * i + 1] != 0) nonzero = 1;
    __syncthreads();
    if (threadIdx.x == 0) g_is64 = (nonzero == 0);
}

// ---------------- graph preprocessing --------------------------------------
__global__ void k_zero_deg() {
    int i = blockIdx.x * blockDim.x + threadIdx.x;
    if (i < N_NODES) g_deg[i] = 0;
}

__global__ void k_hist(const int* __restrict__ e32) {
    int e = blockIdx.x * blockDim.x + threadIdx.x;
    if (e < N_EDGES) {
        int d = edge_at(e32, N_EDGES + e);
        if ((unsigned)d < N_NODES) atomicAdd(&g_deg[d], 1);
    }
}

__global__ void k_scan1() {
    __shared__ int sh[SCAN_B];
    int t = threadIdx.x;
    int i = blockIdx.x * SCAN_B + t;
    int v = (i < N_NODES) ? g_deg[i] : 0;
    sh[t] = v;
    __syncthreads();
    for (int s = 1; s < SCAN_B; s <<= 1) {
        int prev = (t >= s) ? sh[t - s] : 0;
        __syncthreads();
        sh[t] += prev;
        __syncthreads();
    }
    if (i < N_NODES) g_off[i] = sh[t] - v;
    if (t == SCAN_B - 1) g_bsums[blockIdx.x] = sh[t];
}

__global__ void k_scan2() {
    __shared__ int sh[128];
    int t = threadIdx.x;
    int v = (t < NB_SCAN) ? g_bsums[t] : 0;
    sh[t] = v;
    __syncthreads();
#pragma unroll
    for (int s = 1; s < 128; s <<= 1) {
        int prev = (t >= s) ? sh[t - s] : 0;
        __syncthreads();
        sh[t] += prev;
        __syncthreads();
    }
    if (t < NB_SCAN) g_bsums[t] = sh[t] - v;   // exclusive
}

__global__ void k_scan3() {
    int i = blockIdx.x * blockDim.x + threadIdx.x;
    if (i < N_NODES) {
        int o = g_off[i] + g_bsums[i >> 10];
        g_off[i] = o;
        g_cursor[i] = o;
        int d = g_deg[i];
        g_invdeg[i] = 1.0f / (float)(d > 1 ? d : 1);
    }
    if (i == 0) g_off[N_NODES] = N_EDGES;
}

__global__ void k_fill_csc(const int* __restrict__ e32) {
    int e = blockIdx.x * blockDim.x + threadIdx.x;
    if (e < N_EDGES) {
        int s = edge_at(e32, e);
        int d = edge_at(e32, N_EDGES + e);
        if ((unsigned)s < N_NODES && (unsigned)d < N_NODES) {
            int p = atomicAdd(&g_cursor[d], 1);
            g_csc[p] = s;
        }
    }
}

// ---------------- weight rounding: ALL layers, one launch -------------------
__global__ void k_round_w(const float* __restrict__ Wl0, const float* __restrict__ Wr0,
                          const float* __restrict__ Wl1, const float* __restrict__ Wr1,
                          const float* __restrict__ Wl2, const float* __restrict__ Wr2) {
    int i = blockIdx.x * blockDim.x + threadIdx.x;
    if (i < DIMF * DIMF) {
        g_W0l[i] = __float2bfloat16(Wl0[i]);
        g_W0r[i] = __float2bfloat16(Wr0[i]);
        g_W1l[i] = __float2bfloat16(Wl1[i]);
        g_W1r[i] = __float2bfloat16(Wr1[i]);
    }
    if (i < OUTD_F * DIMF) {
        g_W2[i]                 = __float2bfloat16(Wl2[i]);
        g_W2[OUTD_F * DIMF + i] = __float2bfloat16(Wr2[i]);
    }
}

// ---------------- tensor-core GEMM ------------------------------------------
__device__ __forceinline__ void mma_bf16(float* d, const unsigned* a, unsigned b0, unsigned b1) {
    asm volatile(
        "mma.sync.aligned.m16n8k16.row.col.f32.bf16.bf16.f32 "
        "{%0,%1,%2,%3}, {%4,%5,%6,%7}, {%8,%9}, {%0,%1,%2,%3};\n"
        : "+f"(d[0]), "+f"(d[1]), "+f"(d[2]), "+f"(d[3])
        : "r"(a[0]), "r"(a[1]), "r"(a[2]), "r"(a[3]), "r"(b0), "r"(b1));
}

// layers 0/1: blockIdx.y==0 -> U(bf16) = X@Wl^T ; ==1 -> V(f32) = X@Wr^T + b
// single-pass bf16. FP32A: layer 0 reads fp32 x directly.
template <bool FP32A>
__global__ void __launch_bounds__(256) k_gemm_l01(const float* __restrict__ xin,
                                                  const float* __restrict__ bias, int layer) {
    constexpr int OUTD = 128;
    constexpr int MT = 2, NT = 8, STR = 20;

    __shared__ __align__(16) unsigned sAh[128 * STR];
    __shared__ __align__(16) unsigned sWh[OUTD * STR];

    int side = blockIdx.y;
    const unsigned* Ah = (const unsigned*)g_xhi;
    const unsigned* Wh;
    if (layer == 0) Wh = (const unsigned*)(side ? g_W0r : g_W0l);
    else            Wh = (const unsigned*)(side ? g_W1r : g_W1l);

    int tid  = threadIdx.x;
    int wid  = tid >> 5, lane = tid & 31;
    int mw   = wid & 3, nw = wid >> 2;
    int row0 = blockIdx.x * 128;
    int lg   = lane >> 2, lt = lane & 3;

    float acc[MT][NT][4];
#pragma unroll
    for (int m = 0; m < MT; m++)
#pragma unroll
        for (int n = 0; n < NT; n++)
#pragma unroll
            for (int q = 0; q < 4; q++) acc[m][n][q] = 0.f;

#pragma unroll 1
    for (int kt = 0; kt < 4; kt++) {
        int kw = kt * 16;

        if (FP32A) {
#pragma unroll
            for (int i = tid; i < 1024; i += 256) {
                int r = i >> 3, q = (i & 7) * 4;
                float4 v = make_float4(0.f, 0.f, 0.f, 0.f);
                if (row0 + r < N_NODES)
                    v = *(const float4*)(xin + (size_t)(row0 + r) * DIMF + kt * 32 + q);
                int wq = q >> 1;
                sAh[r * STR + wq]     = bf_pack(v.x, v.y);
                sAh[r * STR + wq + 1] = bf_pack(v.z, v.w);
            }
        } else {
#pragma unroll
            for (int i = tid; i < 128 * 4; i += 256) {
                int r = i >> 2, q = (i & 3) * 4;
                uint4 vh = make_uint4(0, 0, 0, 0);
                if (row0 + r < N_NODES)
                    vh = *(const uint4*)(Ah + (size_t)(row0 + r) * 64 + kw + q);
                *(uint4*)(sAh + r * STR + q) = vh;
            }
        }
        for (int i = tid; i < OUTD * 4; i += 256) {
            int r = i >> 2, q = (i & 3) * 4;
            *(uint4*)(sWh + r * STR + q) = *(const uint4*)(Wh + (size_t)r * 64 + kw + q);
        }
        __syncthreads();

#pragma unroll
        for (int ks = 0; ks < 2; ks++) {
            int wb = ks * 8;
            unsigned ah[MT][4];
#pragma unroll
            for (int m = 0; m < MT; m++) {
                int rr = (mw * MT + m) * 16 + lg;
                ah[m][0] = sAh[rr * STR + wb + lt];
                ah[m][1] = sAh[(rr + 8) * STR + wb + lt];
                ah[m][2] = sAh[rr * STR + wb + 4 + lt];
                ah[m][3] = sAh[(rr + 8) * STR + wb + 4 + lt];
            }
#pragma unroll
            for (int n = 0; n < NT; n++) {
                int nr = nw * NT * 8 + n * 8 + lg;
                unsigned bh0 = sWh[nr * STR + wb + lt];
                unsigned bh1 = sWh[nr * STR + wb + 4 + lt];
#pragma unroll
                for (int m = 0; m < MT; m++)
                    mma_bf16(acc[m][n], ah[m], bh0, bh1);
            }
        }
        __syncthreads();
    }

#pragma unroll
    for (int m = 0; m < MT; m++) {
        int r = row0 + (mw * MT + m) * 16 + lg;
#pragma unroll
        for (int n = 0; n < NT; n++) {
            int c = nw * NT * 8 + n * 8 + lt * 2;
#pragma unroll
            for (int h = 0; h < 2; h++) {
                int rr = r + h * 8;
                if (rr >= N_NODES) continue;
                float v0 = acc[m][n][h * 2], v1 = acc[m][n][h * 2 + 1];
                if (side) {
                    g_V[(size_t)rr * OUTD + c]     = v0 + bias[c];
                    g_V[(size_t)rr * OUTD + c + 1] = v1 + bias[c + 1];
                } else {
                    *(unsigned*)(g_Ub + (size_t)rr * OUTD + c) = bf_pack(v0, v1);
                }
            }
        }
    }
}

// layer 2: [u|v] = h1 @ [Wl2;Wr2]^T; u -> fp16, v -> f32 + bias. single-pass.
__global__ void __launch_bounds__(256) k_gemm2(const float* __restrict__ bias) {
    constexpr int OUTD = 80;
    constexpr int MT = 2, NT = 5, STR = 20;

    __shared__ __align__(16) unsigned sAh[128 * STR];
    __shared__ __align__(16) unsigned sWh[OUTD * STR];

    int tid  = threadIdx.x;
    int wid  = tid >> 5, lane = tid & 31;
    int mw   = wid & 3, nw = wid >> 2;
    int row0 = blockIdx.x * 128;
    int lg   = lane >> 2, lt = lane & 3;

    float acc[MT][NT][4];
#pragma unroll
    for (int m = 0; m < MT; m++)
#pragma unroll
        for (int n = 0; n < NT; n++)
#pragma unroll
            for (int q = 0; q < 4; q++) acc[m][n][q] = 0.f;

    const unsigned* Ah = (const unsigned*)g_xhi;
    const unsigned* Wh = (const unsigned*)g_W2;

#pragma unroll 1
    for (int kt = 0; kt < 4; kt++) {
        int kw = kt * 16;

#pragma unroll
        for (int i = tid; i < 128 * 4; i += 256) {
            int r = i >> 2, q = (i & 3) * 4;
            uint4 vh = make_uint4(0, 0, 0, 0);
            if (row0 + r < N_NODES)
                vh = *(const uint4*)(Ah + (size_t)(row0 + r) * 64 + kw + q);
            *(uint4*)(sAh + r * STR + q) = vh;
        }
        for (int i = tid; i < OUTD * 4; i += 256) {
            int r = i >> 2, q = (i & 3) * 4;
            *(uint4*)(sWh + r * STR + q) = *(const uint4*)(Wh + (size_t)r * 64 + kw + q);
        }
        __syncthreads();

#pragma unroll
        for (int ks = 0; ks < 2; ks++) {
            int wb = ks * 8;
            unsigned ah[MT][4];
#pragma unroll
            for (int m = 0; m < MT; m++) {
                int rr = (mw * MT + m) * 16 + lg;
                ah[m][0] = sAh[rr * STR + wb + lt];
                ah[m][1] = sAh[(rr + 8) * STR + wb + lt];
                ah[m][2] = sAh[rr * STR + wb + 4 + lt];
                ah[m][3] = sAh[(rr + 8) * STR + wb + 4 + lt];
            }
#pragma unroll
            for (int n = 0; n < NT; n++) {
                int nr = nw * NT * 8 + n * 8 + lg;
                unsigned bh0 = sWh[nr * STR + wb + lt];
                unsigned bh1 = sWh[nr * STR + wb + 4 + lt];
#pragma unroll
                for (int m = 0; m < MT; m++)
                    mma_bf16(acc[m][n], ah[m], bh0, bh1);
            }
        }
        __syncthreads();
    }

#pragma unroll
    for (int m = 0; m < MT; m++) {
        int r = row0 + (mw * MT + m) * 16 + lg;
#pragma unroll
        for (int n = 0; n < NT; n++) {
            int c = nw * NT * 8 + n * 8 + lt * 2;
#pragma unroll
            for (int h = 0; h < 2; h++) {
                int rr = r + h * 8;
                if (rr >= N_NODES) continue;
                float v0 = acc[m][n][h * 2], v1 = acc[m][n][h * 2 + 1];
                if (c < OUTD_F) {
                    *(__half2*)(g_uh + (size_t)rr * OUTD_F + c) = __floats2half2_rn(v0, v1);
                } else {
                    g_v[(size_t)rr * OUTD_F + c - OUTD_F]     = v0 + bias[c - OUTD_F];
                    g_v[(size_t)rr * OUTD_F + c - OUTD_F + 1] = v1 + bias[c - OUTD_F + 1];
                }
            }
        }
    }
}

// ---------------- fused: gather-mean(U bf16) + V, L2-norm, ReLU, bf16 ------
__global__ void k_aggnorm() {
    int warp = (blockIdx.x * blockDim.x + threadIdx.x) >> 5;
    int lane = threadIdx.x & 31;
    if (warp >= N_NODES) return;
    int n = warp;
    const uint2* __restrict__ U2 = (const uint2*)g_Ub;
    const int* __restrict__ csc = g_csc;
    int j = g_off[n], je = g_off[n + 1];
    float ax = 0.f, ay = 0.f, az = 0.f, aw = 0.f;

    int s0 = 0, s1 = 0, s2 = 0, s3 = 0;
    if (j + 3 < je) {
        s0 = __ldg(&csc[j]);     s1 = __ldg(&csc[j + 1]);
        s2 = __ldg(&csc[j + 2]); s3 = __ldg(&csc[j + 3]);
    }
    while (j + 3 < je) {
        uint2 w0 = __ldg(&U2[(size_t)s0 * 32 + lane]);
        uint2 w1 = __ldg(&U2[(size_t)s1 * 32 + lane]);
        uint2 w2 = __ldg(&U2[(size_t)s2 * 32 + lane]);
        uint2 w3 = __ldg(&U2[(size_t)s3 * 32 + lane]);
        int jn = j + 4;
        if (jn + 3 < je) {
            s0 = __ldg(&csc[jn]);     s1 = __ldg(&csc[jn + 1]);
            s2 = __ldg(&csc[jn + 2]); s3 = __ldg(&csc[jn + 3]);
        }
        ax += bf_lo(w0.x) + bf_lo(w1.x) + bf_lo(w2.x) + bf_lo(w3.x);
        ay += bf_hi(w0.x) + bf_hi(w1.x) + bf_hi(w2.x) + bf_hi(w3.x);
        az += bf_lo(w0.y) + bf_lo(w1.y) + bf_lo(w2.y) + bf_lo(w3.y);
        aw += bf_hi(w0.y) + bf_hi(w1.y) + bf_hi(w2.y) + bf_hi(w3.y);
        j = jn;
    }
    for (; j < je; j++) {
        uint2 w0 = __ldg(&U2[(size_t)__ldg(&csc[j]) * 32 + lane]);
        ax += bf_lo(w0.x); ay += bf_hi(w0.x);
        az += bf_lo(w0.y); aw += bf_hi(w0.y);
    }
    float inv_d = g_invdeg[n];
    float4 vv = ((const float4*)g_V)[(size_t)n * 32 + lane];
    ax = ax * inv_d + vv.x;
    ay = ay * inv_d + vv.y;
    az = az * inv_d + vv.z;
    aw = aw * inv_d + vv.w;

    float ss = ax * ax + ay * ay + az * az + aw * aw;
#pragma unroll
    for (int s = 16; s; s >>= 1) ss += __shfl_xor_sync(0xFFFFFFFFu, ss, s);
    float sc = 1.0f / fmaxf(sqrtf(ss), 1e-12f);
    ax = fmaxf(ax * sc, 0.f);
    ay = fmaxf(ay * sc, 0.f);
    az = fmaxf(az * sc, 0.f);
    aw = fmaxf(aw * sc, 0.f);

    size_t widx = ((size_t)n * DIMF + lane * 4) >> 1;
    unsigned* xo = (unsigned*)g_xhi;
    xo[widx]     = bf_pack(ax, ay);
    xo[widx + 1] = bf_pack(az, aw);
}

// ---------------- layer-2: gather u(fp16), add v, softmax ------------------
__global__ void k_agg_softmax(float* __restrict__ out) {
    int warp = (blockIdx.x * blockDim.x + threadIdx.x) >> 5;
    int lane = threadIdx.x & 31;
    if (warp >= N_NODES) return;
    int n = warp;
    bool act = lane < 20;
    const __half2* __restrict__ u2 = (const __half2*)g_uh;
    const int* __restrict__ csc = g_csc;
    int j = g_off[n], je = g_off[n + 1];
    float acc0 = 0.f, acc1 = 0.f;

    int s0 = 0, s1 = 0, s2 = 0, s3 = 0;
    if (j + 3 < je) {
        s0 = __ldg(&csc[j]);     s1 = __ldg(&csc[j + 1]);
        s2 = __ldg(&csc[j + 2]); s3 = __ldg(&csc[j + 3]);
    }
    while (j + 3 < je) {
        float2 f0, f1, f2, f3;
        if (act) {
            f0 = __half22float2(__ldg(&u2[(size_t)s0 * 20 + lane]));
            f1 = __half22float2(__ldg(&u2[(size_t)s1 * 20 + lane]));
            f2 = __half22float2(__ldg(&u2[(size_t)s2 * 20 + lane]));
            f3 = __half22float2(__ldg(&u2[(size_t)s3 * 20 + lane]));
        }
        int jn = j + 4;
        if (jn + 3 < je) {
            s0 = __ldg(&csc[jn]);     s1 = __ldg(&csc[jn + 1]);
            s2 = __ldg(&csc[jn + 2]); s3 = __ldg(&csc[jn + 3]);
        }
        if (act) {
            acc0 += f0.x + f1.x + f2.x + f3.x;
            acc1 += f0.y + f1.y + f2.y + f3.y;
        }
        j = jn;
    }
    for (; j < je; j++) {
        int s = __ldg(&csc[j]);
        if (act) {
            float2 f0 = __half22float2(__ldg(&u2[(size_t)s * 20 + lane]));
            acc0 += f0.x; acc1 += f0.y;
        }
    }
    float inv_d = g_invdeg[n];
    float a0 = -1e30f, a1 = -1e30f;
    if (act) {
        a0 = acc0 * inv_d + g_v[(size_t)n * OUTD_F + lane * 2];
        a1 = acc1 * inv_d + g_v[(size_t)n * OUTD_F + lane * 2 + 1];
    }
    float m = fmaxf(a0, a1);
#pragma unroll
    for (int s = 16; s; s >>= 1) m = fmaxf(m, __shfl_xor_sync(0xFFFFFFFFu, m, s));
    float e0 = act ? __expf(a0 - m) : 0.f;
    float e1 = act ? __expf(a1 - m) : 0.f;
    float sum = e0 + e1;
#pragma unroll
    for (int s = 16; s; s >>= 1) sum += __shfl_xor_sync(0xFFFFFFFFu, sum, s);
    float inv = 1.0f / sum;
    if (act) {
        float* row = out + (size_t)n * OUTD_F + lane * 2;
        row[0] = e0 * inv;
        row[1] = e1 * inv;
    }
}

// ---------------- launch ----------------------------------------------------
extern "C" void kernel_launch(void* const* d_in, const int* in_sizes, int n_in,
                              void* d_out, int out_size) {
    const float* x   = (const float*)d_in[0];
    const int*   e32 = (const int*)d_in[1];
    const float* Wl0 = (const float*)d_in[2];
    const float* Wr0 = (const float*)d_in[3];
    const float* b0  = (const float*)d_in[4];
    const float* Wl1 = (const float*)d_in[5];
    const float* Wr1 = (const float*)d_in[6];
    const float* b1  = (const float*)d_in[7];
    const float* Wl2 = (const float*)d_in[8];
    const float* Wr2 = (const float*)d_in[9];
    const float* b2  = (const float*)d_in[10];
    float* out = (float*)d_out;

    const int TB = 256;
    int nblk_nodes = (N_NODES + TB - 1) / TB;
    int nblk_edges = (N_EDGES + TB - 1) / TB;
    int nblk_gemm  = (N_NODES + 127) / 128;    // 782
    int nblk_wnode = (N_NODES + 7) / 8;        // warp-per-node
    int nblk_w     = (DIMF * DIMF + TB - 1) / TB;

    // fork a side stream for the CSC build (independent of layer-0 GEMM).
    // streams/events intentionally leaked (destroying mid-capture is illegal).
    cudaStream_t side;
    cudaEvent_t evFork, evCsc;
    cudaStreamCreateWithFlags(&side, cudaStreamNonBlocking);
    cudaEventCreateWithFlags(&evFork, cudaEventDisableTiming);
    cudaEventCreateWithFlags(&evCsc, cudaEventDisableTiming);

    cudaEventRecord(evFork, 0);
    cudaStreamWaitEvent(side, evFork, 0);

    // ---- side stream: dtype detect + CSC build ----
    k_detect<<<1, TB, 0, side>>>(e32);
    k_zero_deg<<<nblk_nodes, TB, 0, side>>>();
    k_hist<<<nblk_edges, TB, 0, side>>>(e32);
    k_scan1<<<NB_SCAN, SCAN_B, 0, side>>>();
    k_scan2<<<1, 128, 0, side>>>();
    k_scan3<<<nblk_nodes, TB, 0, side>>>();
    k_fill_csc<<<nblk_edges, TB, 0, side>>>(e32);
    cudaEventRecord(evCsc, side);

    // ---- main stream: weight rounding (1 launch) + layer-0 GEMM ----
    k_round_w<<<nblk_w, TB>>>(Wl0, Wr0, Wl1, Wr1, Wl2, Wr2);
    k_gemm_l01<true><<<dim3(nblk_gemm, 2), TB>>>(x, b0, 0);

    // ---- join: aggnorm needs CSC + U/V ----
    cudaStreamWaitEvent(0, evCsc, 0);
    k_aggnorm<<<nblk_wnode, TB>>>();

    // ---- layer 1 ----
    k_gemm_l01<false><<<dim3(nblk_gemm, 2), TB>>>(nullptr, b1, 1);
    k_aggnorm<<<nblk_wnode, TB>>>();

    // ---- layer 2 ----
    k_gemm2<<<nblk_gemm, TB>>>(b2);
    k_agg_softmax<<<nblk_wnode, TB>>>(out);
}